// round 9
// baseline (speedup 1.0000x reference)
#include <cuda_runtime.h>
#include <cuda_fp16.h>
#include <math.h>
#include <stdint.h>

// Problem constants
#define L_DIM   2048
#define E_DIM   512
#define EPT_DIM 300
#define H_DIM   16
#define KBIG    (H_DIM * EPT_DIM)   // 4800

// Scratch (allocation-free rule: __device__ globals)
__device__ float  g_Z  [L_DIM * KBIG];   // fp32 Z (fixup); after fixup reused as CSR
__device__ __half g_Zh [L_DIM * KBIG];   // fp16 Z (zzt input)
__device__ float  g_S  [L_DIM * L_DIM];  // scores; after softmax reused as T fp32
__device__ __half g_Ahi[L_DIM * E_DIM];  // Lemb / X1 splits (A operand)
__device__ __half g_Alo[L_DIM * E_DIM];
__device__ __half g_Whi[E_DIM * E_DIM];  // W^T splits
__device__ __half g_Wlo[E_DIM * E_DIM];
__device__ int    g_nnz[L_DIM];

#define MAXB (1 << 18)
#define BANDW 1e-4f
__device__ int  g_cnt;
__device__ int2 g_list[MAXB];

// ===========================================================================
// Helpers
// ===========================================================================
__device__ __forceinline__ uint32_t smem_u32(const void* p) {
    uint32_t a;
    asm("{ .reg .u64 t; cvta.to.shared.u64 t, %1; cvt.u32.u64 %0, t; }"
        : "=r"(a) : "l"(p));
    return a;
}
__device__ __forceinline__ void ldsm_x4(uint32_t* r, uint32_t addr) {
    asm volatile("ldmatrix.sync.aligned.m8n8.x4.shared.b16 {%0,%1,%2,%3}, [%4];"
                 : "=r"(r[0]), "=r"(r[1]), "=r"(r[2]), "=r"(r[3]) : "r"(addr));
}
__device__ __forceinline__ void mma_f16(float* d, const uint32_t* a,
                                        const uint32_t* b) {
    asm volatile("mma.sync.aligned.m16n8k16.row.col.f32.f16.f16.f32 "
                 "{%0,%1,%2,%3}, {%4,%5,%6,%7}, {%8,%9}, {%0,%1,%2,%3};"
                 : "+f"(d[0]), "+f"(d[1]), "+f"(d[2]), "+f"(d[3])
                 : "r"(a[0]), "r"(a[1]), "r"(a[2]), "r"(a[3]),
                   "r"(b[0]), "r"(b[1]));
}
#define CP_ASYNC16(dst, src) \
    asm volatile("cp.async.cg.shared.global [%0], [%1], 16;" \
                 :: "r"(dst), "l"(src))
#define CP_COMMIT()  asm volatile("cp.async.commit_group;" ::: "memory")
#define CP_WAIT(N)   asm volatile("cp.async.wait_group " #N ";" ::: "memory")

__device__ __forceinline__ void split16(float v, __half& hi, __half& lo) {
    hi = __float2half_rn(v);
    lo = __float2half_rn(v - __half2float(hi));
}

// ===========================================================================
// Kernel 1: Z (fp32) + Zh (fp16). Warp per (l, h).
// ===========================================================================
__global__ __launch_bounds__(512) void compute_z(
    const float* __restrict__ xpt, const float* __restrict__ Wpt,
    float* __restrict__ Z, __half* __restrict__ Zh)
{
    const int l    = blockIdx.x;
    const int h    = threadIdx.x >> 5;
    const int lane = threadIdx.x & 31;

    const float* xrow = xpt + (size_t)l * EPT_DIM;
    const float* wrow = Wpt + h * EPT_DIM;

    float v[10];
    float ss = 0.f;
    #pragma unroll
    for (int i = 0; i < 10; i++) {
        int e = lane + i * 32;
        float vv = 0.f;
        if (e < EPT_DIM) {
            float w = wrow[e];
            vv = xrow[e] * w * w;
        }
        v[i] = vv;
        ss += vv * vv;
    }
    #pragma unroll
    for (int o = 16; o; o >>= 1) ss += __shfl_xor_sync(0xffffffffu, ss, o);
    float inv = 0.25f / fmaxf(sqrtf(ss), 1e-12f);

    size_t base = (size_t)l * KBIG + h * EPT_DIM;
    #pragma unroll
    for (int i = 0; i < 10; i++) {
        int e = lane + i * 32;
        if (e < EPT_DIM) {
            float val = v[i] * inv;
            Z[base + e]  = val;
            Zh[base + e] = __float2half_rn(val);
        }
    }
}

// ===========================================================================
// Kernel 2: ZZ^T single-pass fp16 mma.sync; 3-stage cp.async; symmetric.
// ===========================================================================
#define TILE_B   16384
#define STAGE_B  (2 * TILE_B)
#define ZZT_SMEM (3 * STAGE_B + 128)

__global__ void __launch_bounds__(256, 1) zzt_mma(
    const __half* __restrict__ Zh, float* __restrict__ S)
{
    const int bx = blockIdx.x, by = blockIdx.y;
    if (bx < by) return;
    extern __shared__ char smem_raw[];
    const uint32_t sb = (smem_u32(smem_raw) + 127u) & ~127u;

    const int tid  = threadIdx.x;
    const int wid  = tid >> 5, lane = tid & 31;
    const int bm = by << 7, bn = bx << 7;
    const int wm = wid >> 2, wn = wid & 3;

    float acc[4][4][4];
    #pragma unroll
    for (int mt = 0; mt < 4; mt++)
        #pragma unroll
        for (int nt = 0; nt < 4; nt++)
            #pragma unroll
            for (int f = 0; f < 4; f++) acc[mt][nt][f] = 0.f;

    uint32_t offA[4][4], offBp[2][4];
    #pragma unroll
    for (int mt = 0; mt < 4; mt++) {
        int r  = wm * 64 + mt * 16 + (lane & 15);
        int r7 = r & 7;
        #pragma unroll
        for (int ks = 0; ks < 4; ks++) {
            int ch = ks * 2 + (lane >> 4);
            offA[mt][ks] = r * 128 + ((ch ^ r7) << 4);
        }
    }
    #pragma unroll
    for (int p = 0; p < 2; p++) {
        int ntl = p * 2 + ((lane >> 4) & 1);
        int r   = wn * 32 + ntl * 8 + (lane & 7);
        int r7  = r & 7;
        #pragma unroll
        for (int ks = 0; ks < 4; ks++) {
            int ch = ks * 2 + ((lane >> 3) & 1);
            offBp[p][ks] = r * 128 + ((ch ^ r7) << 4);
        }
    }

    uint32_t dstoff[4];
    int      srcA[4], srcB[4];
    #pragma unroll
    for (int t = 0; t < 4; t++) {
        int idx = tid + t * 256;
        int r = idx >> 3, ch = idx & 7;
        dstoff[t] = (uint32_t)(r * 128 + ((ch ^ (r & 7)) << 4));
        srcA[t] = (bm + r) * KBIG + ch * 8;
        srcB[t] = (bn + r) * KBIG + ch * 8;
    }

    auto cp_stage = [&](int s, int kt) {
        const int k0 = kt << 6;
        const uint32_t base = sb + (uint32_t)s * STAGE_B;
        #pragma unroll
        for (int t = 0; t < 4; t++) {
            CP_ASYNC16(base + dstoff[t],          Zh + srcA[t] + k0);
            CP_ASYNC16(base + TILE_B + dstoff[t], Zh + srcB[t] + k0);
        }
        CP_COMMIT();
    };

    auto compute = [&](int s) {
        const uint32_t pa = sb + (uint32_t)s * STAGE_B;
        #pragma unroll
        for (int ks = 0; ks < 4; ks++) {
            uint32_t ah[4][4];
            #pragma unroll
            for (int mt = 0; mt < 4; mt++)
                ldsm_x4(ah[mt], pa + offA[mt][ks]);
            #pragma unroll
            for (int p = 0; p < 2; p++) {
                uint32_t bh[4];
                ldsm_x4(bh, pa + TILE_B + offBp[p][ks]);
                #pragma unroll
                for (int half = 0; half < 2; half++) {
                    int nt = p * 2 + half;
                    #pragma unroll
                    for (int mt = 0; mt < 4; mt++)
                        mma_f16(acc[mt][nt], ah[mt], bh + 2 * half);
                }
            }
        }
    };

    const int NKT = KBIG / 64;   // 75
    cp_stage(0, 0);
    cp_stage(1, 1);
    int sc = 0, s2 = 2;
    for (int kt = 0; kt < NKT; kt++) {
        if (kt + 1 < NKT) { CP_WAIT(1); } else { CP_WAIT(0); }
        __syncthreads();
        if (kt + 2 < NKT) cp_stage(s2, kt + 2);
        compute(sc);
        if (++sc == 3) sc = 0;
        if (++s2 == 3) s2 = 0;
    }

    #pragma unroll
    for (int mt = 0; mt < 4; mt++)
        #pragma unroll
        for (int nt = 0; nt < 4; nt++) {
            const int r0 = bm + wm * 64 + mt * 16 + (lane >> 2);
            const int c0 = bn + wn * 32 + nt * 8 + (lane & 3) * 2;
            const float* d = acc[mt][nt];
            *(float2*)(S + (size_t)r0 * L_DIM + c0)       = make_float2(d[0], d[1]);
            *(float2*)(S + (size_t)(r0 + 8) * L_DIM + c0) = make_float2(d[2], d[3]);
            if (bx != by) {
                S[(size_t)c0 * L_DIM + r0]           = d[0];
                S[(size_t)(c0 + 1) * L_DIM + r0]     = d[1];
                S[(size_t)c0 * L_DIM + r0 + 8]       = d[2];
                S[(size_t)(c0 + 1) * L_DIM + r0 + 8] = d[3];
            }
            #pragma unroll
            for (int f = 0; f < 4; f++) {
                if (fabsf(d[f] - 0.1f) < BANDW) {
                    int rr = r0 + (f >> 1) * 8;
                    int cc = c0 + (f & 1);
                    int p = atomicAdd(&g_cnt, 1);
                    if (p < MAXB) g_list[p] = make_int2(rr, cc);
                    if (bx != by) {
                        p = atomicAdd(&g_cnt, 1);
                        if (p < MAXB) g_list[p] = make_int2(cc, rr);
                    }
                }
            }
        }
}

// ===========================================================================
// Fixup: exact fp32 recompute, one CTA (128 threads) per entry
// ===========================================================================
__global__ void zero_cnt() { g_cnt = 0; }

__global__ __launch_bounds__(128) void fixup_band(
    const float* __restrict__ Z, float* __restrict__ S)
{
    __shared__ float red[4];
    const int tid = threadIdx.x, lid = tid & 31, wid = tid >> 5;
    int cnt = g_cnt; if (cnt > MAXB) cnt = MAXB;
    for (int e = blockIdx.x; e < cnt; e += gridDim.x) {
        int2 ij = g_list[e];
        const float4* a = (const float4*)(Z + (size_t)ij.x * KBIG);
        const float4* b = (const float4*)(Z + (size_t)ij.y * KBIG);
        float s = 0.f;
        #pragma unroll 5
        for (int k = tid; k < KBIG / 4; k += 128) {
            float4 av = a[k], bv = b[k];
            s = fmaf(av.x, bv.x, fmaf(av.y, bv.y,
                fmaf(av.z, bv.z, fmaf(av.w, bv.w, s))));
        }
        #pragma unroll
        for (int o = 16; o; o >>= 1) s += __shfl_xor_sync(0xffffffffu, s, o);
        if (lid == 0) red[wid] = s;
        __syncthreads();
        if (tid == 0)
            S[(size_t)ij.x * L_DIM + ij.y] = red[0] + red[1] + red[2] + red[3];
        __syncthreads();
    }
}

// ===========================================================================
// Masked softmax -> CSR (cols, vals padded rows of stride L_DIM) + nnz
// ===========================================================================
__global__ __launch_bounds__(256) void masked_softmax_csr(
    const float* __restrict__ S,
    int* __restrict__ cols, float* __restrict__ vals, int* __restrict__ nnzs)
{
    __shared__ float red[8];
    __shared__ int cnt;
    const int r   = blockIdx.x;
    const int tid = threadIdx.x;
    const float* row = S + (size_t)r * L_DIM;

    float v[8];
    #pragma unroll
    for (int i = 0; i < 8; i++) v[i] = row[tid + i * 256];

    float m = -1e30f;
    #pragma unroll
    for (int i = 0; i < 8; i++)
        if (v[i] >= 0.1f) m = fmaxf(m, v[i]);
    #pragma unroll
    for (int o = 16; o; o >>= 1) m = fmaxf(m, __shfl_xor_sync(0xffffffffu, m, o));
    if ((tid & 31) == 0) red[tid >> 5] = m;
    if (tid == 0) cnt = 0;
    __syncthreads();
    float M = fmaxf(fmaxf(fmaxf(red[0], red[1]), fmaxf(red[2], red[3])),
                    fmaxf(fmaxf(red[4], red[5]), fmaxf(red[6], red[7])));
    __syncthreads();

    float sum = 0.f;
    #pragma unroll
    for (int i = 0; i < 8; i++) {
        v[i] = (v[i] >= 0.1f) ? expf(v[i] - M) : 0.f;   // kept <=> v[i] > 0
        sum += v[i];
    }
    #pragma unroll
    for (int o = 16; o; o >>= 1) sum += __shfl_xor_sync(0xffffffffu, sum, o);
    if ((tid & 31) == 0) red[tid >> 5] = sum;
    __syncthreads();
    float T = red[0] + red[1] + red[2] + red[3] +
              red[4] + red[5] + red[6] + red[7];
    float inv = 1.f / T;

    int*   rc = cols + (size_t)r * L_DIM;
    float* rv = vals + (size_t)r * L_DIM;
    #pragma unroll
    for (int i = 0; i < 8; i++) {
        if (v[i] > 0.f) {
            int pos = atomicAdd(&cnt, 1);
            rc[pos] = tid + i * 256;
            rv[pos] = v[i] * inv;
        }
    }
    __syncthreads();
    if (tid == 0) nnzs[r] = cnt;
}

// ===========================================================================
// Conversions
// ===========================================================================
__global__ __launch_bounds__(256) void split_rows(
    const float* __restrict__ A, __half* __restrict__ Ahi,
    __half* __restrict__ Alo, int n)
{
    int i = blockIdx.x * 256 + threadIdx.x;
    if (i < n) {
        __half hb, lb;
        split16(A[i], hb, lb);
        Ahi[i] = hb; Alo[i] = lb;
    }
}

__global__ __launch_bounds__(256) void conv_wt(
    const float* __restrict__ W, __half* __restrict__ Whi,
    __half* __restrict__ Wlo)
{
    __shared__ float t[32][33];
    const int bx = blockIdx.x * 32, by = blockIdx.y * 32;
    const int x = threadIdx.x & 31, y4 = (threadIdx.x >> 5) * 4;
    #pragma unroll
    for (int i = 0; i < 4; i++)
        t[y4 + i][x] = W[(size_t)(by + y4 + i) * E_DIM + bx + x];
    __syncthreads();
    #pragma unroll
    for (int i = 0; i < 4; i++) {
        float v = t[x][y4 + i];
        __half hb, lb;
        split16(v, hb, lb);
        size_t o = (size_t)(bx + y4 + i) * E_DIM + by + x;
        Whi[o] = hb; Wlo[o] = lb;
    }
}

// ===========================================================================
// split_mma_rm: T = A @ W (A [2048,512] hi/lo, W^T [512,512] hi/lo),
// 3-pass fp16, fp32 row-major output [2048, 512].
// ===========================================================================
#define GA_B 16384
#define GB_B 8192
#define GSTAGE_B (2 * GA_B + 2 * GB_B)
#define GCN_SMEM (3 * GSTAGE_B + 128)

__global__ void __launch_bounds__(256, 1) split_mma_rm(
    const __half* __restrict__ Ahi, const __half* __restrict__ Alo,
    const __half* __restrict__ Bhi, const __half* __restrict__ Blo,
    float* __restrict__ Tf)
{
    const int K = E_DIM;   // 512
    extern __shared__ char smem_raw[];
    const uint32_t sb = (smem_u32(smem_raw) + 127u) & ~127u;

    const int tid  = threadIdx.x;
    const int wid  = tid >> 5, lane = tid & 31;
    const int bm = blockIdx.y << 7;
    const int bn = blockIdx.x << 6;
    const int wm = wid >> 2, wn = wid & 3;

    float acc[4][2][4];
    #pragma unroll
    for (int mt = 0; mt < 4; mt++)
        #pragma unroll
        for (int nt = 0; nt < 2; nt++)
            #pragma unroll
            for (int f = 0; f < 4; f++) acc[mt][nt][f] = 0.f;

    uint32_t offA[4][4], offB[4];
    #pragma unroll
    for (int mt = 0; mt < 4; mt++) {
        int r  = wm * 64 + mt * 16 + (lane & 15);
        int r7 = r & 7;
        #pragma unroll
        for (int ks = 0; ks < 4; ks++) {
            int ch = ks * 2 + (lane >> 4);
            offA[mt][ks] = r * 128 + ((ch ^ r7) << 4);
        }
    }
    {
        int ntl = (lane >> 4) & 1;
        int r   = wn * 16 + ntl * 8 + (lane & 7);
        int r7  = r & 7;
        #pragma unroll
        for (int ks = 0; ks < 4; ks++) {
            int ch = ks * 2 + ((lane >> 3) & 1);
            offB[ks] = r * 128 + ((ch ^ r7) << 4);
        }
    }

    uint32_t dstA[4]; int srcA[4];
    #pragma unroll
    for (int t = 0; t < 4; t++) {
        int idx = tid + t * 256;
        int r = idx >> 3, ch = idx & 7;
        dstA[t] = (uint32_t)(r * 128 + ((ch ^ (r & 7)) << 4));
        srcA[t] = (bm + r) * K + ch * 8;
    }
    uint32_t dstB[2]; int srcB[2];
    #pragma unroll
    for (int t = 0; t < 2; t++) {
        int idx = tid + t * 256;
        int r = idx >> 3, ch = idx & 7;
        dstB[t] = (uint32_t)(r * 128 + ((ch ^ (r & 7)) << 4));
        srcB[t] = (bn + r) * K + ch * 8;
    }

    auto cp_stage = [&](int s, int kt) {
        const int k0 = kt << 6;
        const uint32_t base = sb + (uint32_t)s * GSTAGE_B;
        #pragma unroll
        for (int t = 0; t < 4; t++) {
            CP_ASYNC16(base + dstA[t],        Ahi + srcA[t] + k0);
            CP_ASYNC16(base + GA_B + dstA[t], Alo + srcA[t] + k0);
        }
        #pragma unroll
        for (int t = 0; t < 2; t++) {
            CP_ASYNC16(base + 2 * GA_B + dstB[t],        Bhi + srcB[t] + k0);
            CP_ASYNC16(base + 2 * GA_B + GB_B + dstB[t], Blo + srcB[t] + k0);
        }
        CP_COMMIT();
    };

    auto compute = [&](int s) {
        const uint32_t pa = sb + (uint32_t)s * GSTAGE_B;
        #pragma unroll
        for (int ks = 0; ks < 4; ks++) {
            uint32_t ahi[4][4], alo[4][4], bh[4], bl[4];
            #pragma unroll
            for (int mt = 0; mt < 4; mt++) {
                ldsm_x4(ahi[mt], pa + offA[mt][ks]);
                ldsm_x4(alo[mt], pa + GA_B + offA[mt][ks]);
            }
            ldsm_x4(bh, pa + 2 * GA_B + offB[ks]);
            ldsm_x4(bl, pa + 2 * GA_B + GB_B + offB[ks]);
            #pragma unroll
            for (int nt = 0; nt < 2; nt++)
                #pragma unroll
                for (int mt = 0; mt < 4; mt++) {
                    mma_f16(acc[mt][nt], ahi[mt], bh + 2 * nt);
                    mma_f16(acc[mt][nt], ahi[mt], bl + 2 * nt);
                    mma_f16(acc[mt][nt], alo[mt], bh + 2 * nt);
                }
        }
    };

    const int NKT = K / 64;   // 8
    cp_stage(0, 0);
    cp_stage(1, 1);
    int sc = 0, s2 = 2;
    for (int kt = 0; kt < NKT; kt++) {
        if (kt + 1 < NKT) { CP_WAIT(1); } else { CP_WAIT(0); }
        __syncthreads();
        if (kt + 2 < NKT) cp_stage(s2, kt + 2);
        compute(sc);
        if (++sc == 3) sc = 0;
        if (++s2 == 3) s2 = 0;
    }

    #pragma unroll
    for (int mt = 0; mt < 4; mt++)
        #pragma unroll
        for (int nt = 0; nt < 2; nt++) {
            const int r0 = bm + wm * 64 + mt * 16 + (lane >> 2);
            const int c0 = bn + wn * 16 + nt * 8 + (lane & 3) * 2;
            const float* d = acc[mt][nt];
            *(float2*)(Tf + (size_t)r0 * E_DIM + c0)       = make_float2(d[0], d[1]);
            *(float2*)(Tf + (size_t)(r0 + 8) * E_DIM + c0) = make_float2(d[2], d[3]);
        }
}

// ===========================================================================
// SPMM: out[r,:] = relu( sum_i vals[r,i] * T[cols[r,i], :] ), exact fp32.
// One CTA (128 threads) per row; thread t owns columns 4t..4t+3.
// OUT_SPLIT=1 -> fp16 hi/lo row-major; OUT_SPLIT=0 -> fp32 out.
// ===========================================================================
template <int OUT_SPLIT>
__global__ __launch_bounds__(128) void spmm(
    const int* __restrict__ cols, const float* __restrict__ vals,
    const int* __restrict__ nnzs, const float* __restrict__ T,
    float* __restrict__ out, __half* __restrict__ Xhi, __half* __restrict__ Xlo)
{
    const int r = blockIdx.x;
    const int t = threadIdx.x;
    const int nnz = nnzs[r];
    const int*   rc = cols + (size_t)r * L_DIM;
    const float* rv = vals + (size_t)r * L_DIM;

    float4 a0 = {0,0,0,0}, a1 = {0,0,0,0}, a2 = {0,0,0,0}, a3 = {0,0,0,0};

    int i = 0;
    for (; i + 4 <= nnz; i += 4) {
        int   c0 = rc[i], c1 = rc[i+1], c2 = rc[i+2], c3 = rc[i+3];
        float v0 = rv[i], v1 = rv[i+1], v2 = rv[i+2], v3 = rv[i+3];
        float4 t0 = *(const float4*)(T + (size_t)c0 * E_DIM + 4 * t);
        float4 t1 = *(const float4*)(T + (size_t)c1 * E_DIM + 4 * t);
        float4 t2 = *(const float4*)(T + (size_t)c2 * E_DIM + 4 * t);
        float4 t3 = *(const float4*)(T + (size_t)c3 * E_DIM + 4 * t);
        a0.x = fmaf(v0, t0.x, a0.x); a0.y = fmaf(v0, t0.y, a0.y);
        a0.z = fmaf(v0, t0.z, a0.z); a0.w = fmaf(v0, t0.w, a0.w);
        a1.x = fmaf(v1, t1.x, a1.x); a1.y = fmaf(v1, t1.y, a1.y);
        a1.z = fmaf(v1, t1.z, a1.z); a1.w = fmaf(v1, t1.w, a1.w);
        a2.x = fmaf(v2, t2.x, a2.x); a2.y = fmaf(v2, t2.y, a2.y);
        a2.z = fmaf(v2, t2.z, a2.z); a2.w = fmaf(v2, t2.w, a2.w);
        a3.x = fmaf(v3, t3.x, a3.x); a3.y = fmaf(v3, t3.y, a3.y);
        a3.z = fmaf(v3, t3.z, a3.z); a3.w = fmaf(v3, t3.w, a3.w);
    }
    for (; i < nnz; i++) {
        int c = rc[i]; float v = rv[i];
        float4 tv = *(const float4*)(T + (size_t)c * E_DIM + 4 * t);
        a0.x = fmaf(v, tv.x, a0.x); a0.y = fmaf(v, tv.y, a0.y);
        a0.z = fmaf(v, tv.z, a0.z); a0.w = fmaf(v, tv.w, a0.w);
    }

    float4 s;
    s.x = fmaxf((a0.x + a1.x) + (a2.x + a3.x), 0.f);
    s.y = fmaxf((a0.y + a1.y) + (a2.y + a3.y), 0.f);
    s.z = fmaxf((a0.z + a1.z) + (a2.z + a3.z), 0.f);
    s.w = fmaxf((a0.w + a1.w) + (a2.w + a3.w), 0.f);

    if (OUT_SPLIT) {
        __half h0, l0, h1, l1, h2, l2, h3, l3;
        split16(s.x, h0, l0); split16(s.y, h1, l1);
        split16(s.z, h2, l2); split16(s.w, h3, l3);
        *(__half2*)(Xhi + (size_t)r * E_DIM + 4 * t)     = __halves2half2(h0, h1);
        *(__half2*)(Xhi + (size_t)r * E_DIM + 4 * t + 2) = __halves2half2(h2, h3);
        *(__half2*)(Xlo + (size_t)r * E_DIM + 4 * t)     = __halves2half2(l0, l1);
        *(__half2*)(Xlo + (size_t)r * E_DIM + 4 * t + 2) = __halves2half2(l2, l3);
    } else {
        *(float4*)(out + (size_t)r * E_DIM + 4 * t) = s;
    }
}

// ===========================================================================
// Launch
// ===========================================================================
extern "C" void kernel_launch(void* const* d_in, const int* in_sizes, int n_in,
                              void* d_out, int out_size)
{
    const float* Lemb = (const float*)d_in[0];
    const float* Xpt  = (const float*)d_in[1];
    const float* Wpt  = (const float*)d_in[2];
    const float* W0   = (const float*)d_in[3];
    const float* W1   = (const float*)d_in[4];
    float* out = (float*)d_out;

    float *Z, *S;
    __half *Zh, *Ahi, *Alo, *Whi, *Wlo;
    int* nnzs;
    cudaGetSymbolAddress((void**)&Z,    g_Z);
    cudaGetSymbolAddress((void**)&Zh,   g_Zh);
    cudaGetSymbolAddress((void**)&S,    g_S);
    cudaGetSymbolAddress((void**)&Ahi,  g_Ahi);
    cudaGetSymbolAddress((void**)&Alo,  g_Alo);
    cudaGetSymbolAddress((void**)&Whi,  g_Whi);
    cudaGetSymbolAddress((void**)&Wlo,  g_Wlo);
    cudaGetSymbolAddress((void**)&nnzs, g_nnz);

    // buffer reuse: g_Z (dead after fixup) -> CSR arrays; g_S (dead after
    // softmax) -> dense T fp32 [2048 x 512]
    int*   cols = (int*)Z;
    float* vals = (float*)Z + (size_t)L_DIM * L_DIM;
    float* Tf   = S;

    cudaFuncSetAttribute(zzt_mma, cudaFuncAttributeMaxDynamicSharedMemorySize,
                         ZZT_SMEM);
    cudaFuncSetAttribute(split_mma_rm,
                         cudaFuncAttributeMaxDynamicSharedMemorySize, GCN_SMEM);

    zero_cnt<<<1, 1>>>();

    // 1) Z fp32 + Zh fp16
    compute_z<<<L_DIM, 512>>>(Xpt, Wpt, Z, Zh);

    // 2) scores = Z Z^T (single-pass fp16 mma), band scan fused
    zzt_mma<<<dim3(16, 16), 256, ZZT_SMEM>>>(Zh, S);

    // 3) exact fp32 fixup of near-threshold entries
    fixup_band<<<1024, 128>>>(Z, S);

    // 4) adj = softmax(threshold(scores)) -> CSR (overwrites g_Z region)
    masked_softmax_csr<<<L_DIM, 256>>>(S, cols, vals, nnzs);

    // 5) input conversions for layer 1
    split_rows<<<(L_DIM * E_DIM + 255) / 256, 256>>>(Lemb, Ahi, Alo,
                                                     L_DIM * E_DIM);
    conv_wt<<<dim3(16, 16), 256>>>(W0, Whi, Wlo);

    // 6) T0 = Lemb @ W0 (fp32 row-major, into dead g_S)
    split_mma_rm<<<dim3(E_DIM / 64, L_DIM / 128), 256, GCN_SMEM>>>(
        Ahi, Alo, Whi, Wlo, Tf);

    // 7) X1 = relu(adj @ T0) exact fp32 SPMM -> fp16 hi/lo (overwrites Ahi/Alo)
    spmm<1><<<L_DIM, 128>>>(cols, vals, nnzs, Tf, nullptr, Ahi, Alo);

    // 8) T1 = X1 @ W1 (fp32 row-major)
    conv_wt<<<dim3(16, 16), 256>>>(W1, Whi, Wlo);
    split_mma_rm<<<dim3(E_DIM / 64, L_DIM / 128), 256, GCN_SMEM>>>(
        Ahi, Alo, Whi, Wlo, Tf);

    // 9) out = relu(adj @ T1) exact fp32 SPMM
    spmm<0><<<L_DIM, 128>>>(cols, vals, nnzs, Tf, out, nullptr, nullptr);
}

// round 10
// speedup vs baseline: 1.1123x; 1.1123x over previous
#include <cuda_runtime.h>
#include <cuda_fp16.h>
#include <math.h>
#include <stdint.h>

// Problem constants
#define L_DIM   2048
#define E_DIM   512
#define EPT_DIM 300
#define H_DIM   16
#define KBIG    (H_DIM * EPT_DIM)   // 4800

// Scratch (allocation-free rule: __device__ globals)
__device__ __half g_Zh [L_DIM * KBIG];   // fp16 Z (zzt input)
__device__ float  g_inv[L_DIM * H_DIM];  // per-(l,h) 0.25/norm
__device__ float  g_S  [L_DIM * L_DIM];  // scores
__device__ __half g_Phi[L_DIM * L_DIM];  // adj hi
__device__ __half g_Plo[L_DIM * L_DIM];  // adj lo
__device__ __half g_Ahi[L_DIM * E_DIM];  // Lemb / X1 splits
__device__ __half g_Alo[L_DIM * E_DIM];
__device__ __half g_Whi[2 * E_DIM * E_DIM]; // W0^T, W1^T hi
__device__ __half g_Wlo[2 * E_DIM * E_DIM]; // W0^T, W1^T lo
__device__ __half g_Thi[E_DIM * L_DIM];  // T^T splits (B operand of gcn)
__device__ __half g_Tlo[E_DIM * L_DIM];

#define MAXB (1 << 18)
#define BANDW 1e-4f
__device__ int  g_cnt;
__device__ int2 g_list[MAXB];

// ===========================================================================
// Helpers
// ===========================================================================
__device__ __forceinline__ uint32_t smem_u32(const void* p) {
    uint32_t a;
    asm("{ .reg .u64 t; cvta.to.shared.u64 t, %1; cvt.u32.u64 %0, t; }"
        : "=r"(a) : "l"(p));
    return a;
}
__device__ __forceinline__ void ldsm_x4(uint32_t* r, uint32_t addr) {
    asm volatile("ldmatrix.sync.aligned.m8n8.x4.shared.b16 {%0,%1,%2,%3}, [%4];"
                 : "=r"(r[0]), "=r"(r[1]), "=r"(r[2]), "=r"(r[3]) : "r"(addr));
}
__device__ __forceinline__ void mma_f16(float* d, const uint32_t* a,
                                        const uint32_t* b) {
    asm volatile("mma.sync.aligned.m16n8k16.row.col.f32.f16.f16.f32 "
                 "{%0,%1,%2,%3}, {%4,%5,%6,%7}, {%8,%9}, {%0,%1,%2,%3};"
                 : "+f"(d[0]), "+f"(d[1]), "+f"(d[2]), "+f"(d[3])
                 : "r"(a[0]), "r"(a[1]), "r"(a[2]), "r"(a[3]),
                   "r"(b[0]), "r"(b[1]));
}
#define CP_ASYNC16(dst, src) \
    asm volatile("cp.async.cg.shared.global [%0], [%1], 16;" \
                 :: "r"(dst), "l"(src))
#define CP_COMMIT()  asm volatile("cp.async.commit_group;" ::: "memory")
#define CP_WAIT(N)   asm volatile("cp.async.wait_group " #N ";" ::: "memory")

__device__ __forceinline__ void split16(float v, __half& hi, __half& lo) {
    hi = __float2half_rn(v);
    lo = __float2half_rn(v - __half2float(hi));
}

// ===========================================================================
// Kernel 1: Zh (fp16) + inv norms. Warp per (l, h). Also resets g_cnt.
// ===========================================================================
__global__ __launch_bounds__(512) void compute_z(
    const float* __restrict__ xpt, const float* __restrict__ Wpt,
    __half* __restrict__ Zh, float* __restrict__ invs)
{
    const int l    = blockIdx.x;
    const int h    = threadIdx.x >> 5;
    const int lane = threadIdx.x & 31;
    if (l == 0 && threadIdx.x == 0) g_cnt = 0;

    const float* xrow = xpt + (size_t)l * EPT_DIM;
    const float* wrow = Wpt + h * EPT_DIM;

    float v[10];
    float ss = 0.f;
    #pragma unroll
    for (int i = 0; i < 10; i++) {
        int e = lane + i * 32;
        float vv = 0.f;
        if (e < EPT_DIM) {
            float w = wrow[e];
            vv = xrow[e] * w * w;
        }
        v[i] = vv;
        ss += vv * vv;
    }
    #pragma unroll
    for (int o = 16; o; o >>= 1) ss += __shfl_xor_sync(0xffffffffu, ss, o);
    float inv = 0.25f / fmaxf(sqrtf(ss), 1e-12f);
    if (lane == 0) invs[l * H_DIM + h] = inv;

    size_t base = (size_t)l * KBIG + h * EPT_DIM;
    #pragma unroll
    for (int i = 0; i < 10; i++) {
        int e = lane + i * 32;
        if (e < EPT_DIM)
            Zh[base + e] = __float2half_rn(v[i] * inv);
    }
}

// ===========================================================================
// Kernel 2: ZZ^T single-pass fp16 mma.sync; 3-stage cp.async; symmetric.
// ===========================================================================
#define TILE_B   16384
#define STAGE_B  (2 * TILE_B)
#define ZZT_SMEM (3 * STAGE_B + 128)

__global__ void __launch_bounds__(256, 1) zzt_mma(
    const __half* __restrict__ Zh, float* __restrict__ S)
{
    const int bx = blockIdx.x, by = blockIdx.y;
    if (bx < by) return;
    extern __shared__ char smem_raw[];
    const uint32_t sb = (smem_u32(smem_raw) + 127u) & ~127u;

    const int tid  = threadIdx.x;
    const int wid  = tid >> 5, lane = tid & 31;
    const int bm = by << 7, bn = bx << 7;
    const int wm = wid >> 2, wn = wid & 3;

    float acc[4][4][4];
    #pragma unroll
    for (int mt = 0; mt < 4; mt++)
        #pragma unroll
        for (int nt = 0; nt < 4; nt++)
            #pragma unroll
            for (int f = 0; f < 4; f++) acc[mt][nt][f] = 0.f;

    uint32_t offA[4][4], offBp[2][4];
    #pragma unroll
    for (int mt = 0; mt < 4; mt++) {
        int r  = wm * 64 + mt * 16 + (lane & 15);
        int r7 = r & 7;
        #pragma unroll
        for (int ks = 0; ks < 4; ks++) {
            int ch = ks * 2 + (lane >> 4);
            offA[mt][ks] = r * 128 + ((ch ^ r7) << 4);
        }
    }
    #pragma unroll
    for (int p = 0; p < 2; p++) {
        int ntl = p * 2 + ((lane >> 4) & 1);
        int r   = wn * 32 + ntl * 8 + (lane & 7);
        int r7  = r & 7;
        #pragma unroll
        for (int ks = 0; ks < 4; ks++) {
            int ch = ks * 2 + ((lane >> 3) & 1);
            offBp[p][ks] = r * 128 + ((ch ^ r7) << 4);
        }
    }

    uint32_t dstoff[4];
    int      srcA[4], srcB[4];
    #pragma unroll
    for (int t = 0; t < 4; t++) {
        int idx = tid + t * 256;
        int r = idx >> 3, ch = idx & 7;
        dstoff[t] = (uint32_t)(r * 128 + ((ch ^ (r & 7)) << 4));
        srcA[t] = (bm + r) * KBIG + ch * 8;
        srcB[t] = (bn + r) * KBIG + ch * 8;
    }

    auto cp_stage = [&](int s, int kt) {
        const int k0 = kt << 6;
        const uint32_t base = sb + (uint32_t)s * STAGE_B;
        #pragma unroll
        for (int t = 0; t < 4; t++) {
            CP_ASYNC16(base + dstoff[t],          Zh + srcA[t] + k0);
            CP_ASYNC16(base + TILE_B + dstoff[t], Zh + srcB[t] + k0);
        }
        CP_COMMIT();
    };

    auto compute = [&](int s) {
        const uint32_t pa = sb + (uint32_t)s * STAGE_B;
        #pragma unroll
        for (int ks = 0; ks < 4; ks++) {
            uint32_t ah[4][4];
            #pragma unroll
            for (int mt = 0; mt < 4; mt++)
                ldsm_x4(ah[mt], pa + offA[mt][ks]);
            #pragma unroll
            for (int p = 0; p < 2; p++) {
                uint32_t bh[4];
                ldsm_x4(bh, pa + TILE_B + offBp[p][ks]);
                #pragma unroll
                for (int half = 0; half < 2; half++) {
                    int nt = p * 2 + half;
                    #pragma unroll
                    for (int mt = 0; mt < 4; mt++)
                        mma_f16(acc[mt][nt], ah[mt], bh + 2 * half);
                }
            }
        }
    };

    const int NKT = KBIG / 64;   // 75
    cp_stage(0, 0);
    cp_stage(1, 1);
    int sc = 0, s2 = 2;
    for (int kt = 0; kt < NKT; kt++) {
        if (kt + 1 < NKT) { CP_WAIT(1); } else { CP_WAIT(0); }
        __syncthreads();
        if (kt + 2 < NKT) cp_stage(s2, kt + 2);
        compute(sc);
        if (++sc == 3) sc = 0;
        if (++s2 == 3) s2 = 0;
    }

    #pragma unroll
    for (int mt = 0; mt < 4; mt++)
        #pragma unroll
        for (int nt = 0; nt < 4; nt++) {
            const int r0 = bm + wm * 64 + mt * 16 + (lane >> 2);
            const int c0 = bn + wn * 32 + nt * 8 + (lane & 3) * 2;
            const float* d = acc[mt][nt];
            *(float2*)(S + (size_t)r0 * L_DIM + c0)       = make_float2(d[0], d[1]);
            *(float2*)(S + (size_t)(r0 + 8) * L_DIM + c0) = make_float2(d[2], d[3]);
            if (bx != by) {
                S[(size_t)c0 * L_DIM + r0]           = d[0];
                S[(size_t)(c0 + 1) * L_DIM + r0]     = d[1];
                S[(size_t)c0 * L_DIM + r0 + 8]       = d[2];
                S[(size_t)(c0 + 1) * L_DIM + r0 + 8] = d[3];
            }
            #pragma unroll
            for (int f = 0; f < 4; f++) {
                if (fabsf(d[f] - 0.1f) < BANDW) {
                    int rr = r0 + (f >> 1) * 8;
                    int cc = c0 + (f & 1);
                    int p = atomicAdd(&g_cnt, 1);
                    if (p < MAXB) g_list[p] = make_int2(rr, cc);
                    if (bx != by) {
                        p = atomicAdd(&g_cnt, 1);
                        if (p < MAXB) g_list[p] = make_int2(cc, rr);
                    }
                }
            }
        }
}

// ===========================================================================
// Fixup: exact fp32 recompute from raw inputs (no fp32 Z needed).
// One CTA (128 threads) per entry; thread t: h = t>>3, 8 lanes per h.
// score = sum_h inv_ih * inv_jh * sum_e (x_i w^2)(x_j w^2)
// ===========================================================================
__global__ __launch_bounds__(128) void fixup_band(
    const float* __restrict__ xpt, const float* __restrict__ Wpt,
    const float* __restrict__ invs, float* __restrict__ S)
{
    __shared__ float sxi[EPT_DIM], sxj[EPT_DIM];
    __shared__ float hred[H_DIM];
    const int tid = threadIdx.x;
    const int h   = tid >> 3;
    const int sub = tid & 7;
    int cnt = g_cnt; if (cnt > MAXB) cnt = MAXB;

    for (int e = blockIdx.x; e < cnt; e += gridDim.x) {
        int2 ij = g_list[e];
        // stage x rows
        for (int k = tid; k < EPT_DIM; k += 128) {
            sxi[k] = xpt[(size_t)ij.x * EPT_DIM + k];
            sxj[k] = xpt[(size_t)ij.y * EPT_DIM + k];
        }
        __syncthreads();

        const float* wrow = Wpt + h * EPT_DIM;
        float d = 0.f;
        for (int k = sub; k < EPT_DIM; k += 8) {
            float w = __ldg(wrow + k);
            float w2 = w * w;
            float a = sxi[k] * w2;
            float b = sxj[k] * w2;
            d = fmaf(a, b, d);
        }
        d += __shfl_xor_sync(0xffffffffu, d, 4);
        d += __shfl_xor_sync(0xffffffffu, d, 2);
        d += __shfl_xor_sync(0xffffffffu, d, 1);
        if (sub == 0)
            hred[h] = d * invs[ij.x * H_DIM + h] * invs[ij.y * H_DIM + h];
        __syncthreads();
        if (tid == 0) {
            float s = 0.f;
            #pragma unroll
            for (int hh = 0; hh < H_DIM; hh++) s += hred[hh];
            S[(size_t)ij.x * L_DIM + ij.y] = s;
        }
        __syncthreads();
    }
}

// ===========================================================================
// Masked softmax -> adj fp16 hi/lo splits (one pass, row in registers)
// ===========================================================================
__global__ __launch_bounds__(256) void masked_softmax(
    const float* __restrict__ S,
    __half* __restrict__ Phi, __half* __restrict__ Plo)
{
    __shared__ float red[8];
    const int r   = blockIdx.x;
    const int tid = threadIdx.x;
    const float* row = S + (size_t)r * L_DIM;

    float v[8];
    #pragma unroll
    for (int i = 0; i < 8; i++) v[i] = row[tid + i * 256];

    float m = -1e30f;
    #pragma unroll
    for (int i = 0; i < 8; i++)
        if (v[i] >= 0.1f) m = fmaxf(m, v[i]);
    #pragma unroll
    for (int o = 16; o; o >>= 1) m = fmaxf(m, __shfl_xor_sync(0xffffffffu, m, o));
    if ((tid & 31) == 0) red[tid >> 5] = m;
    __syncthreads();
    float M = fmaxf(fmaxf(fmaxf(red[0], red[1]), fmaxf(red[2], red[3])),
                    fmaxf(fmaxf(red[4], red[5]), fmaxf(red[6], red[7])));
    __syncthreads();

    float sum = 0.f;
    #pragma unroll
    for (int i = 0; i < 8; i++) {
        v[i] = (v[i] >= 0.1f) ? expf(v[i] - M) : 0.f;
        sum += v[i];
    }
    #pragma unroll
    for (int o = 16; o; o >>= 1) sum += __shfl_xor_sync(0xffffffffu, sum, o);
    if ((tid & 31) == 0) red[tid >> 5] = sum;
    __syncthreads();
    float T = red[0] + red[1] + red[2] + red[3] +
              red[4] + red[5] + red[6] + red[7];
    float inv = 1.f / T;

    #pragma unroll
    for (int i = 0; i < 8; i++) {
        float p = v[i] * inv;
        __half hb, lb;
        split16(p, hb, lb);
        Phi[(size_t)r * L_DIM + tid + i * 256] = hb;
        Plo[(size_t)r * L_DIM + tid + i * 256] = lb;
    }
}

// ===========================================================================
// Conversions
// ===========================================================================
__global__ __launch_bounds__(256) void split_rows(
    const float* __restrict__ A, __half* __restrict__ Ahi,
    __half* __restrict__ Alo, int n)
{
    int i = blockIdx.x * 256 + threadIdx.x;
    if (i < n) {
        __half hb, lb;
        split16(A[i], hb, lb);
        Ahi[i] = hb; Alo[i] = lb;
    }
}

// both weights in one launch: blockIdx.z selects W0/W1
__global__ __launch_bounds__(256) void conv_wt2(
    const float* __restrict__ W0, const float* __restrict__ W1,
    __half* __restrict__ Whi, __half* __restrict__ Wlo)
{
    __shared__ float t[32][33];
    const float* W = blockIdx.z ? W1 : W0;
    __half* whi = Whi + (size_t)blockIdx.z * E_DIM * E_DIM;
    __half* wlo = Wlo + (size_t)blockIdx.z * E_DIM * E_DIM;
    const int bx = blockIdx.x * 32, by = blockIdx.y * 32;
    const int x = threadIdx.x & 31, y4 = (threadIdx.x >> 5) * 4;
    #pragma unroll
    for (int i = 0; i < 4; i++)
        t[y4 + i][x] = W[(size_t)(by + y4 + i) * E_DIM + bx + x];
    __syncthreads();
    #pragma unroll
    for (int i = 0; i < 4; i++) {
        float v = t[x][y4 + i];
        __half hb, lb;
        split16(v, hb, lb);
        size_t o = (size_t)(bx + y4 + i) * E_DIM + by + x;
        whi[o] = hb; wlo[o] = lb;
    }
}

// ===========================================================================
// split_mma: T = A @ W (A [2048,512] hi/lo, W^T [512,512] hi/lo),
// 3-pass fp16, writes T TRANSPOSED as fp16 hi/lo [512, 2048].
// ===========================================================================
#define GA_B 16384
#define GB_B 8192
#define GSTAGE_B (2 * GA_B + 2 * GB_B)
#define GCN_SMEM (3 * GSTAGE_B + 128)

__global__ void __launch_bounds__(256, 1) split_mma(
    const __half* __restrict__ Ahi, const __half* __restrict__ Alo,
    const __half* __restrict__ Bhi, const __half* __restrict__ Blo,
    __half* __restrict__ Thi, __half* __restrict__ Tlo)
{
    const int K = E_DIM;   // 512
    extern __shared__ char smem_raw[];
    const uint32_t sb = (smem_u32(smem_raw) + 127u) & ~127u;

    const int tid  = threadIdx.x;
    const int wid  = tid >> 5, lane = tid & 31;
    const int bm = blockIdx.y << 7;
    const int bn = blockIdx.x << 6;
    const int wm = wid >> 2, wn = wid & 3;

    float acc[4][2][4];
    #pragma unroll
    for (int mt = 0; mt < 4; mt++)
        #pragma unroll
        for (int nt = 0; nt < 2; nt++)
            #pragma unroll
            for (int f = 0; f < 4; f++) acc[mt][nt][f] = 0.f;

    uint32_t offA[4][4], offB[4];
    #pragma unroll
    for (int mt = 0; mt < 4; mt++) {
        int r  = wm * 64 + mt * 16 + (lane & 15);
        int r7 = r & 7;
        #pragma unroll
        for (int ks = 0; ks < 4; ks++) {
            int ch = ks * 2 + (lane >> 4);
            offA[mt][ks] = r * 128 + ((ch ^ r7) << 4);
        }
    }
    {
        int ntl = (lane >> 4) & 1;
        int r   = wn * 16 + ntl * 8 + (lane & 7);
        int r7  = r & 7;
        #pragma unroll
        for (int ks = 0; ks < 4; ks++) {
            int ch = ks * 2 + ((lane >> 3) & 1);
            offB[ks] = r * 128 + ((ch ^ r7) << 4);
        }
    }

    uint32_t dstA[4]; int srcA[4];
    #pragma unroll
    for (int t = 0; t < 4; t++) {
        int idx = tid + t * 256;
        int r = idx >> 3, ch = idx & 7;
        dstA[t] = (uint32_t)(r * 128 + ((ch ^ (r & 7)) << 4));
        srcA[t] = (bm + r) * K + ch * 8;
    }
    uint32_t dstB[2]; int srcB[2];
    #pragma unroll
    for (int t = 0; t < 2; t++) {
        int idx = tid + t * 256;
        int r = idx >> 3, ch = idx & 7;
        dstB[t] = (uint32_t)(r * 128 + ((ch ^ (r & 7)) << 4));
        srcB[t] = (bn + r) * K + ch * 8;
    }

    auto cp_stage = [&](int s, int kt) {
        const int k0 = kt << 6;
        const uint32_t base = sb + (uint32_t)s * GSTAGE_B;
        #pragma unroll
        for (int t = 0; t < 4; t++) {
            CP_ASYNC16(base + dstA[t],        Ahi + srcA[t] + k0);
            CP_ASYNC16(base + GA_B + dstA[t], Alo + srcA[t] + k0);
        }
        #pragma unroll
        for (int t = 0; t < 2; t++) {
            CP_ASYNC16(base + 2 * GA_B + dstB[t],        Bhi + srcB[t] + k0);
            CP_ASYNC16(base + 2 * GA_B + GB_B + dstB[t], Blo + srcB[t] + k0);
        }
        CP_COMMIT();
    };

    auto compute = [&](int s) {
        const uint32_t pa = sb + (uint32_t)s * GSTAGE_B;
        #pragma unroll
        for (int ks = 0; ks < 4; ks++) {
            uint32_t ahi[4][4], alo[4][4], bh[4], bl[4];
            #pragma unroll
            for (int mt = 0; mt < 4; mt++) {
                ldsm_x4(ahi[mt], pa + offA[mt][ks]);
                ldsm_x4(alo[mt], pa + GA_B + offA[mt][ks]);
            }
            ldsm_x4(bh, pa + 2 * GA_B + offB[ks]);
            ldsm_x4(bl, pa + 2 * GA_B + GB_B + offB[ks]);
            #pragma unroll
            for (int nt = 0; nt < 2; nt++)
                #pragma unroll
                for (int mt = 0; mt < 4; mt++) {
                    mma_f16(acc[mt][nt], ahi[mt], bh + 2 * nt);
                    mma_f16(acc[mt][nt], ahi[mt], bl + 2 * nt);
                    mma_f16(acc[mt][nt], alo[mt], bh + 2 * nt);
                }
        }
    };

    const int NKT = K / 64;   // 8
    cp_stage(0, 0);
    cp_stage(1, 1);
    int sc = 0, s2 = 2;
    for (int kt = 0; kt < NKT; kt++) {
        if (kt + 1 < NKT) { CP_WAIT(1); } else { CP_WAIT(0); }
        __syncthreads();
        if (kt + 2 < NKT) cp_stage(s2, kt + 2);
        compute(sc);
        if (++sc == 3) sc = 0;
        if (++s2 == 3) s2 = 0;
    }

    // transposed split epilogue: Tt[n][m], ld = L_DIM
    #pragma unroll
    for (int mt = 0; mt < 4; mt++)
        #pragma unroll
        for (int nt = 0; nt < 2; nt++) {
            const int r0 = bm + wm * 64 + mt * 16 + (lane >> 2);
            const int c0 = bn + wn * 16 + nt * 8 + (lane & 3) * 2;
            const float* d = acc[mt][nt];
            #pragma unroll
            for (int f = 0; f < 4; f++) {
                int rr = r0 + (f >> 1) * 8;
                int cc = c0 + (f & 1);
                __half hb, lb;
                split16(d[f], hb, lb);
                Thi[(size_t)cc * L_DIM + rr] = hb;
                Tlo[(size_t)cc * L_DIM + rr] = lb;
            }
        }
}

// ===========================================================================
// gcn_mma: C = relu(P @ Tt^T). OUT_SPLIT=1 -> fp16 hi/lo row-major (X1);
// OUT_SPLIT=0 -> fp32 out.
// ===========================================================================
template <int OUT_SPLIT>
__global__ void __launch_bounds__(256, 1) gcn_mma(
    const __half* __restrict__ Ahi, const __half* __restrict__ Alo,
    const __half* __restrict__ Bhi, const __half* __restrict__ Blo,
    float* __restrict__ C, __half* __restrict__ Xhi, __half* __restrict__ Xlo)
{
    const int K = L_DIM;   // 2048
    extern __shared__ char smem_raw[];
    const uint32_t sb = (smem_u32(smem_raw) + 127u) & ~127u;

    const int tid  = threadIdx.x;
    const int wid  = tid >> 5, lane = tid & 31;
    const int bm = blockIdx.y << 7;
    const int bn = blockIdx.x << 6;
    const int wm = wid >> 2, wn = wid & 3;

    float acc[4][2][4];
    #pragma unroll
    for (int mt = 0; mt < 4; mt++)
        #pragma unroll
        for (int nt = 0; nt < 2; nt++)
            #pragma unroll
            for (int f = 0; f < 4; f++) acc[mt][nt][f] = 0.f;

    uint32_t offA[4][4], offB[4];
    #pragma unroll
    for (int mt = 0; mt < 4; mt++) {
        int r  = wm * 64 + mt * 16 + (lane & 15);
        int r7 = r & 7;
        #pragma unroll
        for (int ks = 0; ks < 4; ks++) {
            int ch = ks * 2 + (lane >> 4);
            offA[mt][ks] = r * 128 + ((ch ^ r7) << 4);
        }
    }
    {
        int ntl = (lane >> 4) & 1;
        int r   = wn * 16 + ntl * 8 + (lane & 7);
        int r7  = r & 7;
        #pragma unroll
        for (int ks = 0; ks < 4; ks++) {
            int ch = ks * 2 + ((lane >> 3) & 1);
            offB[ks] = r * 128 + ((ch ^ r7) << 4);
        }
    }

    uint32_t dstA[4]; int srcA[4];
    #pragma unroll
    for (int t = 0; t < 4; t++) {
        int idx = tid + t * 256;
        int r = idx >> 3, ch = idx & 7;
        dstA[t] = (uint32_t)(r * 128 + ((ch ^ (r & 7)) << 4));
        srcA[t] = (bm + r) * K + ch * 8;
    }
    uint32_t dstB[2]; int srcB[2];
    #pragma unroll
    for (int t = 0; t < 2; t++) {
        int idx = tid + t * 256;
        int r = idx >> 3, ch = idx & 7;
        dstB[t] = (uint32_t)(r * 128 + ((ch ^ (r & 7)) << 4));
        srcB[t] = (bn + r) * K + ch * 8;
    }

    auto cp_stage = [&](int s, int kt) {
        const int k0 = kt << 6;
        const uint32_t base = sb + (uint32_t)s * GSTAGE_B;
        #pragma unroll
        for (int t = 0; t < 4; t++) {
            CP_ASYNC16(base + dstA[t],        Ahi + srcA[t] + k0);
            CP_ASYNC16(base + GA_B + dstA[t], Alo + srcA[t] + k0);
        }
        #pragma unroll
        for (int t = 0; t < 2; t++) {
            CP_ASYNC16(base + 2 * GA_B + dstB[t],        Bhi + srcB[t] + k0);
            CP_ASYNC16(base + 2 * GA_B + GB_B + dstB[t], Blo + srcB[t] + k0);
        }
        CP_COMMIT();
    };

    auto compute = [&](int s) {
        const uint32_t pa = sb + (uint32_t)s * GSTAGE_B;
        #pragma unroll
        for (int ks = 0; ks < 4; ks++) {
            uint32_t ahi[4][4], alo[4][4], bh[4], bl[4];
            #pragma unroll
            for (int mt = 0; mt < 4; mt++) {
                ldsm_x4(ahi[mt], pa + offA[mt][ks]);
                ldsm_x4(alo[mt], pa + GA_B + offA[mt][ks]);
            }
            ldsm_x4(bh, pa + 2 * GA_B + offB[ks]);
            ldsm_x4(bl, pa + 2 * GA_B + GB_B + offB[ks]);
            #pragma unroll
            for (int nt = 0; nt < 2; nt++)
                #pragma unroll
                for (int mt = 0; mt < 4; mt++) {
                    mma_f16(acc[mt][nt], ahi[mt], bh + 2 * nt);
                    mma_f16(acc[mt][nt], ahi[mt], bl + 2 * nt);
                    mma_f16(acc[mt][nt], alo[mt], bh + 2 * nt);
                }
        }
    };

    const int NKT = K / 64;   // 32
    cp_stage(0, 0);
    cp_stage(1, 1);
    int sc = 0, s2 = 2;
    for (int kt = 0; kt < NKT; kt++) {
        if (kt + 1 < NKT) { CP_WAIT(1); } else { CP_WAIT(0); }
        __syncthreads();
        if (kt + 2 < NKT) cp_stage(s2, kt + 2);
        compute(sc);
        if (++sc == 3) sc = 0;
        if (++s2 == 3) s2 = 0;
    }

    #pragma unroll
    for (int mt = 0; mt < 4; mt++)
        #pragma unroll
        for (int nt = 0; nt < 2; nt++) {
            const int r0 = bm + wm * 64 + mt * 16 + (lane >> 2);
            const int c0 = bn + wn * 16 + nt * 8 + (lane & 3) * 2;
            const float* d = acc[mt][nt];
            #pragma unroll
            for (int hrow = 0; hrow < 2; hrow++) {
                float v0 = fmaxf(d[hrow * 2 + 0], 0.f);
                float v1 = fmaxf(d[hrow * 2 + 1], 0.f);
                int rr = r0 + hrow * 8;
                if (OUT_SPLIT) {
                    __half h0, l0, h1, l1;
                    split16(v0, h0, l0);
                    split16(v1, h1, l1);
                    *(__half2*)(Xhi + (size_t)rr * E_DIM + c0) =
                        __halves2half2(h0, h1);
                    *(__half2*)(Xlo + (size_t)rr * E_DIM + c0) =
                        __halves2half2(l0, l1);
                } else {
                    *(float2*)(C + (size_t)rr * E_DIM + c0) =
                        make_float2(v0, v1);
                }
            }
        }
}

// ===========================================================================
// Launch
// ===========================================================================
extern "C" void kernel_launch(void* const* d_in, const int* in_sizes, int n_in,
                              void* d_out, int out_size)
{
    const float* Lemb = (const float*)d_in[0];
    const float* Xpt  = (const float*)d_in[1];
    const float* Wpt  = (const float*)d_in[2];
    const float* W0   = (const float*)d_in[3];
    const float* W1   = (const float*)d_in[4];
    float* out = (float*)d_out;

    float *S, *invs;
    __half *Zh, *Phi, *Plo, *Ahi, *Alo, *Whi, *Wlo, *Thi, *Tlo;
    cudaGetSymbolAddress((void**)&Zh,   g_Zh);
    cudaGetSymbolAddress((void**)&invs, g_inv);
    cudaGetSymbolAddress((void**)&S,    g_S);
    cudaGetSymbolAddress((void**)&Phi,  g_Phi);
    cudaGetSymbolAddress((void**)&Plo,  g_Plo);
    cudaGetSymbolAddress((void**)&Ahi,  g_Ahi);
    cudaGetSymbolAddress((void**)&Alo,  g_Alo);
    cudaGetSymbolAddress((void**)&Whi,  g_Whi);
    cudaGetSymbolAddress((void**)&Wlo,  g_Wlo);
    cudaGetSymbolAddress((void**)&Thi,  g_Thi);
    cudaGetSymbolAddress((void**)&Tlo,  g_Tlo);

    cudaFuncSetAttribute(zzt_mma, cudaFuncAttributeMaxDynamicSharedMemorySize,
                         ZZT_SMEM);
    cudaFuncSetAttribute(split_mma, cudaFuncAttributeMaxDynamicSharedMemorySize,
                         GCN_SMEM);
    cudaFuncSetAttribute(gcn_mma<0>, cudaFuncAttributeMaxDynamicSharedMemorySize,
                         GCN_SMEM);
    cudaFuncSetAttribute(gcn_mma<1>, cudaFuncAttributeMaxDynamicSharedMemorySize,
                         GCN_SMEM);

    // 1) Zh fp16 + inv norms (+ g_cnt reset)
    compute_z<<<L_DIM, 512>>>(Xpt, Wpt, Zh, invs);

    // 2) scores = Z Z^T (single-pass fp16 mma), band scan fused
    zzt_mma<<<dim3(16, 16), 256, ZZT_SMEM>>>(Zh, S);

    // 3) exact fp32 fixup, recomputed from raw inputs
    fixup_band<<<1024, 128>>>(Xpt, Wpt, invs, S);

    // 4) adj = softmax(threshold(scores)) -> fp16 hi/lo
    masked_softmax<<<L_DIM, 256>>>(S, Phi, Plo);

    // 5) input conversions (Lemb split; both weight transposes in one launch)
    split_rows<<<(L_DIM * E_DIM + 255) / 256, 256>>>(Lemb, Ahi, Alo,
                                                     L_DIM * E_DIM);
    conv_wt2<<<dim3(16, 16, 2), 256>>>(W0, W1, Whi, Wlo);

    // 6) T0t = (Lemb @ W0)^T fp16 hi/lo
    split_mma<<<dim3(E_DIM / 64, L_DIM / 128), 256, GCN_SMEM>>>(
        Ahi, Alo, Whi, Wlo, Thi, Tlo);

    // 7) X1 = relu(adj @ T0) -> fp16 hi/lo (overwrites Ahi/Alo)
    gcn_mma<1><<<dim3(E_DIM / 64, L_DIM / 128), 256, GCN_SMEM>>>(
        Phi, Plo, Thi, Tlo, nullptr, Ahi, Alo);

    // 8) T1t = (X1 @ W1)^T fp16 hi/lo
    split_mma<<<dim3(E_DIM / 64, L_DIM / 128), 256, GCN_SMEM>>>(
        Ahi, Alo, Whi + (size_t)E_DIM * E_DIM, Wlo + (size_t)E_DIM * E_DIM,
        Thi, Tlo);

    // 9) out = relu(adj @ T1) fp32
    gcn_mma<0><<<dim3(E_DIM / 64, L_DIM / 128), 256, GCN_SMEM>>>(
        Phi, Plo, Thi, Tlo, out, nullptr, nullptr);
}

// round 11
// speedup vs baseline: 1.2758x; 1.1470x over previous
#include <cuda_runtime.h>
#include <cuda_fp16.h>
#include <math.h>
#include <stdint.h>

// Problem constants
#define L_DIM   2048
#define E_DIM   512
#define EPT_DIM 300
#define H_DIM   16
#define KBIG    (H_DIM * EPT_DIM)   // 4800

// Scratch (allocation-free rule: __device__ globals)
__device__ __half g_Zh [L_DIM * KBIG];   // fp16 Z (zzt input)
__device__ float  g_inv[L_DIM * H_DIM];  // per-(l,h) 0.25/norm
__device__ float  g_S  [L_DIM * L_DIM];  // scores
__device__ __half g_Phi[L_DIM * L_DIM];  // adj hi (P_lo dropped: 2-pass GCN)
__device__ __half g_Ahi[L_DIM * E_DIM];  // Lemb / X1 splits
__device__ __half g_Alo[L_DIM * E_DIM];
__device__ __half g_Whi[2 * E_DIM * E_DIM]; // W0^T, W1^T hi
__device__ __half g_Wlo[2 * E_DIM * E_DIM]; // W0^T, W1^T lo
__device__ __half g_Thi[E_DIM * L_DIM];  // T^T splits (B operand of gcn)
__device__ __half g_Tlo[E_DIM * L_DIM];

#define MAXB (1 << 18)
#define BANDW 1e-4f
__device__ int  g_cnt;
__device__ int2 g_list[MAXB];

// ===========================================================================
// Helpers
// ===========================================================================
__device__ __forceinline__ uint32_t smem_u32(const void* p) {
    uint32_t a;
    asm("{ .reg .u64 t; cvta.to.shared.u64 t, %1; cvt.u32.u64 %0, t; }"
        : "=r"(a) : "l"(p));
    return a;
}
__device__ __forceinline__ void ldsm_x4(uint32_t* r, uint32_t addr) {
    asm volatile("ldmatrix.sync.aligned.m8n8.x4.shared.b16 {%0,%1,%2,%3}, [%4];"
                 : "=r"(r[0]), "=r"(r[1]), "=r"(r[2]), "=r"(r[3]) : "r"(addr));
}
__device__ __forceinline__ void mma_f16(float* d, const uint32_t* a,
                                        const uint32_t* b) {
    asm volatile("mma.sync.aligned.m16n8k16.row.col.f32.f16.f16.f32 "
                 "{%0,%1,%2,%3}, {%4,%5,%6,%7}, {%8,%9}, {%0,%1,%2,%3};"
                 : "+f"(d[0]), "+f"(d[1]), "+f"(d[2]), "+f"(d[3])
                 : "r"(a[0]), "r"(a[1]), "r"(a[2]), "r"(a[3]),
                   "r"(b[0]), "r"(b[1]));
}
#define CP_ASYNC16(dst, src) \
    asm volatile("cp.async.cg.shared.global [%0], [%1], 16;" \
                 :: "r"(dst), "l"(src))
#define CP_COMMIT()  asm volatile("cp.async.commit_group;" ::: "memory")
#define CP_WAIT(N)   asm volatile("cp.async.wait_group " #N ";" ::: "memory")

__device__ __forceinline__ void split16(float v, __half& hi, __half& lo) {
    hi = __float2half_rn(v);
    lo = __float2half_rn(v - __half2float(hi));
}

// ===========================================================================
// Kernel 1: Zh (fp16) + inv norms. Warp per (l, h). Also resets g_cnt.
// ===========================================================================
__global__ __launch_bounds__(512) void compute_z(
    const float* __restrict__ xpt, const float* __restrict__ Wpt,
    __half* __restrict__ Zh, float* __restrict__ invs)
{
    const int l    = blockIdx.x;
    const int h    = threadIdx.x >> 5;
    const int lane = threadIdx.x & 31;
    if (l == 0 && threadIdx.x == 0) g_cnt = 0;

    const float* xrow = xpt + (size_t)l * EPT_DIM;
    const float* wrow = Wpt + h * EPT_DIM;

    float v[10];
    float ss = 0.f;
    #pragma unroll
    for (int i = 0; i < 10; i++) {
        int e = lane + i * 32;
        float vv = 0.f;
        if (e < EPT_DIM) {
            float w = wrow[e];
            vv = xrow[e] * w * w;
        }
        v[i] = vv;
        ss += vv * vv;
    }
    #pragma unroll
    for (int o = 16; o; o >>= 1) ss += __shfl_xor_sync(0xffffffffu, ss, o);
    float inv = 0.25f / fmaxf(sqrtf(ss), 1e-12f);
    if (lane == 0) invs[l * H_DIM + h] = inv;

    size_t base = (size_t)l * KBIG + h * EPT_DIM;
    #pragma unroll
    for (int i = 0; i < 10; i++) {
        int e = lane + i * 32;
        if (e < EPT_DIM)
            Zh[base + e] = __float2half_rn(v[i] * inv);
    }
}

// ===========================================================================
// Kernel 2: ZZ^T single-pass fp16 mma.sync; 3-stage cp.async; symmetric.
// ===========================================================================
#define TILE_B   16384
#define STAGE_B  (2 * TILE_B)
#define ZZT_SMEM (3 * STAGE_B + 128)

__global__ void __launch_bounds__(256, 1) zzt_mma(
    const __half* __restrict__ Zh, float* __restrict__ S)
{
    const int bx = blockIdx.x, by = blockIdx.y;
    if (bx < by) return;
    extern __shared__ char smem_raw[];
    const uint32_t sb = (smem_u32(smem_raw) + 127u) & ~127u;

    const int tid  = threadIdx.x;
    const int wid  = tid >> 5, lane = tid & 31;
    const int bm = by << 7, bn = bx << 7;
    const int wm = wid >> 2, wn = wid & 3;

    float acc[4][4][4];
    #pragma unroll
    for (int mt = 0; mt < 4; mt++)
        #pragma unroll
        for (int nt = 0; nt < 4; nt++)
            #pragma unroll
            for (int f = 0; f < 4; f++) acc[mt][nt][f] = 0.f;

    uint32_t offA[4][4], offBp[2][4];
    #pragma unroll
    for (int mt = 0; mt < 4; mt++) {
        int r  = wm * 64 + mt * 16 + (lane & 15);
        int r7 = r & 7;
        #pragma unroll
        for (int ks = 0; ks < 4; ks++) {
            int ch = ks * 2 + (lane >> 4);
            offA[mt][ks] = r * 128 + ((ch ^ r7) << 4);
        }
    }
    #pragma unroll
    for (int p = 0; p < 2; p++) {
        int ntl = p * 2 + ((lane >> 4) & 1);
        int r   = wn * 32 + ntl * 8 + (lane & 7);
        int r7  = r & 7;
        #pragma unroll
        for (int ks = 0; ks < 4; ks++) {
            int ch = ks * 2 + ((lane >> 3) & 1);
            offBp[p][ks] = r * 128 + ((ch ^ r7) << 4);
        }
    }

    uint32_t dstoff[4];
    int      srcA[4], srcB[4];
    #pragma unroll
    for (int t = 0; t < 4; t++) {
        int idx = tid + t * 256;
        int r = idx >> 3, ch = idx & 7;
        dstoff[t] = (uint32_t)(r * 128 + ((ch ^ (r & 7)) << 4));
        srcA[t] = (bm + r) * KBIG + ch * 8;
        srcB[t] = (bn + r) * KBIG + ch * 8;
    }

    auto cp_stage = [&](int s, int kt) {
        const int k0 = kt << 6;
        const uint32_t base = sb + (uint32_t)s * STAGE_B;
        #pragma unroll
        for (int t = 0; t < 4; t++) {
            CP_ASYNC16(base + dstoff[t],          Zh + srcA[t] + k0);
            CP_ASYNC16(base + TILE_B + dstoff[t], Zh + srcB[t] + k0);
        }
        CP_COMMIT();
    };

    auto compute = [&](int s) {
        const uint32_t pa = sb + (uint32_t)s * STAGE_B;
        #pragma unroll
        for (int ks = 0; ks < 4; ks++) {
            uint32_t ah[4][4];
            #pragma unroll
            for (int mt = 0; mt < 4; mt++)
                ldsm_x4(ah[mt], pa + offA[mt][ks]);
            #pragma unroll
            for (int p = 0; p < 2; p++) {
                uint32_t bh[4];
                ldsm_x4(bh, pa + TILE_B + offBp[p][ks]);
                #pragma unroll
                for (int half = 0; half < 2; half++) {
                    int nt = p * 2 + half;
                    #pragma unroll
                    for (int mt = 0; mt < 4; mt++)
                        mma_f16(acc[mt][nt], ah[mt], bh + 2 * half);
                }
            }
        }
    };

    const int NKT = KBIG / 64;   // 75
    cp_stage(0, 0);
    cp_stage(1, 1);
    int sc = 0, s2 = 2;
    for (int kt = 0; kt < NKT; kt++) {
        if (kt + 1 < NKT) { CP_WAIT(1); } else { CP_WAIT(0); }
        __syncthreads();
        if (kt + 2 < NKT) cp_stage(s2, kt + 2);
        compute(sc);
        if (++sc == 3) sc = 0;
        if (++s2 == 3) s2 = 0;
    }

    #pragma unroll
    for (int mt = 0; mt < 4; mt++)
        #pragma unroll
        for (int nt = 0; nt < 4; nt++) {
            const int r0 = bm + wm * 64 + mt * 16 + (lane >> 2);
            const int c0 = bn + wn * 32 + nt * 8 + (lane & 3) * 2;
            const float* d = acc[mt][nt];
            *(float2*)(S + (size_t)r0 * L_DIM + c0)       = make_float2(d[0], d[1]);
            *(float2*)(S + (size_t)(r0 + 8) * L_DIM + c0) = make_float2(d[2], d[3]);
            if (bx != by) {
                S[(size_t)c0 * L_DIM + r0]           = d[0];
                S[(size_t)(c0 + 1) * L_DIM + r0]     = d[1];
                S[(size_t)c0 * L_DIM + r0 + 8]       = d[2];
                S[(size_t)(c0 + 1) * L_DIM + r0 + 8] = d[3];
            }
            #pragma unroll
            for (int f = 0; f < 4; f++) {
                if (fabsf(d[f] - 0.1f) < BANDW) {
                    int rr = r0 + (f >> 1) * 8;
                    int cc = c0 + (f & 1);
                    int p = atomicAdd(&g_cnt, 1);
                    if (p < MAXB) g_list[p] = make_int2(rr, cc);
                    if (bx != by) {
                        p = atomicAdd(&g_cnt, 1);
                        if (p < MAXB) g_list[p] = make_int2(cc, rr);
                    }
                }
            }
        }
}

// ===========================================================================
// Fixup: exact fp32 recompute from raw inputs.
// ===========================================================================
__global__ __launch_bounds__(128) void fixup_band(
    const float* __restrict__ xpt, const float* __restrict__ Wpt,
    const float* __restrict__ invs, float* __restrict__ S)
{
    __shared__ float sxi[EPT_DIM], sxj[EPT_DIM];
    __shared__ float hred[H_DIM];
    const int tid = threadIdx.x;
    const int h   = tid >> 3;
    const int sub = tid & 7;
    int cnt = g_cnt; if (cnt > MAXB) cnt = MAXB;

    for (int e = blockIdx.x; e < cnt; e += gridDim.x) {
        int2 ij = g_list[e];
        for (int k = tid; k < EPT_DIM; k += 128) {
            sxi[k] = xpt[(size_t)ij.x * EPT_DIM + k];
            sxj[k] = xpt[(size_t)ij.y * EPT_DIM + k];
        }
        __syncthreads();

        const float* wrow = Wpt + h * EPT_DIM;
        float d = 0.f;
        for (int k = sub; k < EPT_DIM; k += 8) {
            float w = __ldg(wrow + k);
            float w2 = w * w;
            float a = sxi[k] * w2;
            float b = sxj[k] * w2;
            d = fmaf(a, b, d);
        }
        d += __shfl_xor_sync(0xffffffffu, d, 4);
        d += __shfl_xor_sync(0xffffffffu, d, 2);
        d += __shfl_xor_sync(0xffffffffu, d, 1);
        if (sub == 0)
            hred[h] = d * invs[ij.x * H_DIM + h] * invs[ij.y * H_DIM + h];
        __syncthreads();
        if (tid == 0) {
            float s = 0.f;
            #pragma unroll
            for (int hh = 0; hh < H_DIM; hh++) s += hred[hh];
            S[(size_t)ij.x * L_DIM + ij.y] = s;
        }
        __syncthreads();
    }
}

// ===========================================================================
// Masked softmax -> adj fp16 (hi only; P_lo dropped for 2-pass GCN)
// ===========================================================================
__global__ __launch_bounds__(256) void masked_softmax(
    const float* __restrict__ S, __half* __restrict__ Phi)
{
    __shared__ float red[8];
    const int r   = blockIdx.x;
    const int tid = threadIdx.x;
    const float* row = S + (size_t)r * L_DIM;

    float v[8];
    #pragma unroll
    for (int i = 0; i < 8; i++) v[i] = row[tid + i * 256];

    float m = -1e30f;
    #pragma unroll
    for (int i = 0; i < 8; i++)
        if (v[i] >= 0.1f) m = fmaxf(m, v[i]);
    #pragma unroll
    for (int o = 16; o; o >>= 1) m = fmaxf(m, __shfl_xor_sync(0xffffffffu, m, o));
    if ((tid & 31) == 0) red[tid >> 5] = m;
    __syncthreads();
    float M = fmaxf(fmaxf(fmaxf(red[0], red[1]), fmaxf(red[2], red[3])),
                    fmaxf(fmaxf(red[4], red[5]), fmaxf(red[6], red[7])));
    __syncthreads();

    float sum = 0.f;
    #pragma unroll
    for (int i = 0; i < 8; i++) {
        v[i] = (v[i] >= 0.1f) ? expf(v[i] - M) : 0.f;
        sum += v[i];
    }
    #pragma unroll
    for (int o = 16; o; o >>= 1) sum += __shfl_xor_sync(0xffffffffu, sum, o);
    if ((tid & 31) == 0) red[tid >> 5] = sum;
    __syncthreads();
    float T = red[0] + red[1] + red[2] + red[3] +
              red[4] + red[5] + red[6] + red[7];
    float inv = 1.f / T;

    #pragma unroll
    for (int i = 0; i < 8; i++)
        Phi[(size_t)r * L_DIM + tid + i * 256] = __float2half_rn(v[i] * inv);
}

// ===========================================================================
// Conversions
// ===========================================================================
__global__ __launch_bounds__(256) void split_rows(
    const float* __restrict__ A, __half* __restrict__ Ahi,
    __half* __restrict__ Alo, int n)
{
    int i = blockIdx.x * 256 + threadIdx.x;
    if (i < n) {
        __half hb, lb;
        split16(A[i], hb, lb);
        Ahi[i] = hb; Alo[i] = lb;
    }
}

__global__ __launch_bounds__(256) void conv_wt2(
    const float* __restrict__ W0, const float* __restrict__ W1,
    __half* __restrict__ Whi, __half* __restrict__ Wlo)
{
    __shared__ float t[32][33];
    const float* W = blockIdx.z ? W1 : W0;
    __half* whi = Whi + (size_t)blockIdx.z * E_DIM * E_DIM;
    __half* wlo = Wlo + (size_t)blockIdx.z * E_DIM * E_DIM;
    const int bx = blockIdx.x * 32, by = blockIdx.y * 32;
    const int x = threadIdx.x & 31, y4 = (threadIdx.x >> 5) * 4;
    #pragma unroll
    for (int i = 0; i < 4; i++)
        t[y4 + i][x] = W[(size_t)(by + y4 + i) * E_DIM + bx + x];
    __syncthreads();
    #pragma unroll
    for (int i = 0; i < 4; i++) {
        float v = t[x][y4 + i];
        __half hb, lb;
        split16(v, hb, lb);
        size_t o = (size_t)(bx + y4 + i) * E_DIM + by + x;
        whi[o] = hb; wlo[o] = lb;
    }
}

// ===========================================================================
// split_mma: T = A @ W (3-pass fp16), writes T^T as fp16 hi/lo [512, 2048].
// ===========================================================================
#define GA_B 16384
#define GB_B 8192
#define GSTAGE_B (2 * GA_B + 2 * GB_B)
#define SPLIT_SMEM (3 * GSTAGE_B + 128)

__global__ void __launch_bounds__(256, 1) split_mma(
    const __half* __restrict__ Ahi, const __half* __restrict__ Alo,
    const __half* __restrict__ Bhi, const __half* __restrict__ Blo,
    __half* __restrict__ Thi, __half* __restrict__ Tlo)
{
    const int K = E_DIM;   // 512
    extern __shared__ char smem_raw[];
    const uint32_t sb = (smem_u32(smem_raw) + 127u) & ~127u;

    const int tid  = threadIdx.x;
    const int wid  = tid >> 5, lane = tid & 31;
    const int bm = blockIdx.y << 7;
    const int bn = blockIdx.x << 6;
    const int wm = wid >> 2, wn = wid & 3;

    float acc[4][2][4];
    #pragma unroll
    for (int mt = 0; mt < 4; mt++)
        #pragma unroll
        for (int nt = 0; nt < 2; nt++)
            #pragma unroll
            for (int f = 0; f < 4; f++) acc[mt][nt][f] = 0.f;

    uint32_t offA[4][4], offB[4];
    #pragma unroll
    for (int mt = 0; mt < 4; mt++) {
        int r  = wm * 64 + mt * 16 + (lane & 15);
        int r7 = r & 7;
        #pragma unroll
        for (int ks = 0; ks < 4; ks++) {
            int ch = ks * 2 + (lane >> 4);
            offA[mt][ks] = r * 128 + ((ch ^ r7) << 4);
        }
    }
    {
        int ntl = (lane >> 4) & 1;
        int r   = wn * 16 + ntl * 8 + (lane & 7);
        int r7  = r & 7;
        #pragma unroll
        for (int ks = 0; ks < 4; ks++) {
            int ch = ks * 2 + ((lane >> 3) & 1);
            offB[ks] = r * 128 + ((ch ^ r7) << 4);
        }
    }

    uint32_t dstA[4]; int srcA[4];
    #pragma unroll
    for (int t = 0; t < 4; t++) {
        int idx = tid + t * 256;
        int r = idx >> 3, ch = idx & 7;
        dstA[t] = (uint32_t)(r * 128 + ((ch ^ (r & 7)) << 4));
        srcA[t] = (bm + r) * K + ch * 8;
    }
    uint32_t dstB[2]; int srcB[2];
    #pragma unroll
    for (int t = 0; t < 2; t++) {
        int idx = tid + t * 256;
        int r = idx >> 3, ch = idx & 7;
        dstB[t] = (uint32_t)(r * 128 + ((ch ^ (r & 7)) << 4));
        srcB[t] = (bn + r) * K + ch * 8;
    }

    auto cp_stage = [&](int s, int kt) {
        const int k0 = kt << 6;
        const uint32_t base = sb + (uint32_t)s * GSTAGE_B;
        #pragma unroll
        for (int t = 0; t < 4; t++) {
            CP_ASYNC16(base + dstA[t],        Ahi + srcA[t] + k0);
            CP_ASYNC16(base + GA_B + dstA[t], Alo + srcA[t] + k0);
        }
        #pragma unroll
        for (int t = 0; t < 2; t++) {
            CP_ASYNC16(base + 2 * GA_B + dstB[t],        Bhi + srcB[t] + k0);
            CP_ASYNC16(base + 2 * GA_B + GB_B + dstB[t], Blo + srcB[t] + k0);
        }
        CP_COMMIT();
    };

    auto compute = [&](int s) {
        const uint32_t pa = sb + (uint32_t)s * GSTAGE_B;
        #pragma unroll
        for (int ks = 0; ks < 4; ks++) {
            uint32_t ahi[4][4], alo[4][4], bh[4], bl[4];
            #pragma unroll
            for (int mt = 0; mt < 4; mt++) {
                ldsm_x4(ahi[mt], pa + offA[mt][ks]);
                ldsm_x4(alo[mt], pa + GA_B + offA[mt][ks]);
            }
            ldsm_x4(bh, pa + 2 * GA_B + offB[ks]);
            ldsm_x4(bl, pa + 2 * GA_B + GB_B + offB[ks]);
            #pragma unroll
            for (int nt = 0; nt < 2; nt++)
                #pragma unroll
                for (int mt = 0; mt < 4; mt++) {
                    mma_f16(acc[mt][nt], ahi[mt], bh + 2 * nt);
                    mma_f16(acc[mt][nt], ahi[mt], bl + 2 * nt);
                    mma_f16(acc[mt][nt], alo[mt], bh + 2 * nt);
                }
        }
    };

    const int NKT = K / 64;   // 8
    cp_stage(0, 0);
    cp_stage(1, 1);
    int sc = 0, s2 = 2;
    for (int kt = 0; kt < NKT; kt++) {
        if (kt + 1 < NKT) { CP_WAIT(1); } else { CP_WAIT(0); }
        __syncthreads();
        if (kt + 2 < NKT) cp_stage(s2, kt + 2);
        compute(sc);
        if (++sc == 3) sc = 0;
        if (++s2 == 3) s2 = 0;
    }

    #pragma unroll
    for (int mt = 0; mt < 4; mt++)
        #pragma unroll
        for (int nt = 0; nt < 2; nt++) {
            const int r0 = bm + wm * 64 + mt * 16 + (lane >> 2);
            const int c0 = bn + wn * 16 + nt * 8 + (lane & 3) * 2;
            const float* d = acc[mt][nt];
            #pragma unroll
            for (int f = 0; f < 4; f++) {
                int rr = r0 + (f >> 1) * 8;
                int cc = c0 + (f & 1);
                __half hb, lb;
                split16(d[f], hb, lb);
                Thi[(size_t)cc * L_DIM + rr] = hb;
                Tlo[(size_t)cc * L_DIM + rr] = lb;
            }
        }
}

// ===========================================================================
// gcn_mma: C = relu(P @ Tt^T), 2-pass (P hi only; T hi/lo).
// OUT_SPLIT=1 -> fp16 hi/lo row-major (X1); OUT_SPLIT=0 -> fp32 out.
// ===========================================================================
#define QA_B 16384                  // P hi tile: 128 x 128B
#define QB_B 8192                   // T tile: 64 x 128B
#define QSTAGE_B (QA_B + 2 * QB_B)  // 32 KB
#define GCN_SMEM (3 * QSTAGE_B + 128)

template <int OUT_SPLIT>
__global__ void __launch_bounds__(256, 1) gcn_mma(
    const __half* __restrict__ Ph,
    const __half* __restrict__ Bhi, const __half* __restrict__ Blo,
    float* __restrict__ C, __half* __restrict__ Xhi, __half* __restrict__ Xlo)
{
    const int K = L_DIM;   // 2048
    extern __shared__ char smem_raw[];
    const uint32_t sb = (smem_u32(smem_raw) + 127u) & ~127u;

    const int tid  = threadIdx.x;
    const int wid  = tid >> 5, lane = tid & 31;
    const int bm = blockIdx.y << 7;
    const int bn = blockIdx.x << 6;
    const int wm = wid >> 2, wn = wid & 3;

    float acc[4][2][4];
    #pragma unroll
    for (int mt = 0; mt < 4; mt++)
        #pragma unroll
        for (int nt = 0; nt < 2; nt++)
            #pragma unroll
            for (int f = 0; f < 4; f++) acc[mt][nt][f] = 0.f;

    uint32_t offA[4][4], offB[4];
    #pragma unroll
    for (int mt = 0; mt < 4; mt++) {
        int r  = wm * 64 + mt * 16 + (lane & 15);
        int r7 = r & 7;
        #pragma unroll
        for (int ks = 0; ks < 4; ks++) {
            int ch = ks * 2 + (lane >> 4);
            offA[mt][ks] = r * 128 + ((ch ^ r7) << 4);
        }
    }
    {
        int ntl = (lane >> 4) & 1;
        int r   = wn * 16 + ntl * 8 + (lane & 7);
        int r7  = r & 7;
        #pragma unroll
        for (int ks = 0; ks < 4; ks++) {
            int ch = ks * 2 + ((lane >> 3) & 1);
            offB[ks] = r * 128 + ((ch ^ r7) << 4);
        }
    }

    uint32_t dstA[4]; int srcA[4];
    #pragma unroll
    for (int t = 0; t < 4; t++) {
        int idx = tid + t * 256;
        int r = idx >> 3, ch = idx & 7;
        dstA[t] = (uint32_t)(r * 128 + ((ch ^ (r & 7)) << 4));
        srcA[t] = (bm + r) * K + ch * 8;
    }
    uint32_t dstB[2]; int srcB[2];
    #pragma unroll
    for (int t = 0; t < 2; t++) {
        int idx = tid + t * 256;
        int r = idx >> 3, ch = idx & 7;
        dstB[t] = (uint32_t)(r * 128 + ((ch ^ (r & 7)) << 4));
        srcB[t] = (bn + r) * K + ch * 8;
    }

    auto cp_stage = [&](int s, int kt) {
        const int k0 = kt << 6;
        const uint32_t base = sb + (uint32_t)s * QSTAGE_B;
        #pragma unroll
        for (int t = 0; t < 4; t++)
            CP_ASYNC16(base + dstA[t], Ph + srcA[t] + k0);
        #pragma unroll
        for (int t = 0; t < 2; t++) {
            CP_ASYNC16(base + QA_B + dstB[t],        Bhi + srcB[t] + k0);
            CP_ASYNC16(base + QA_B + QB_B + dstB[t], Blo + srcB[t] + k0);
        }
        CP_COMMIT();
    };

    auto compute = [&](int s) {
        const uint32_t pa = sb + (uint32_t)s * QSTAGE_B;
        #pragma unroll
        for (int ks = 0; ks < 4; ks++) {
            uint32_t ah[4][4], bh[4], bl[4];
            #pragma unroll
            for (int mt = 0; mt < 4; mt++)
                ldsm_x4(ah[mt], pa + offA[mt][ks]);
            ldsm_x4(bh, pa + QA_B + offB[ks]);
            ldsm_x4(bl, pa + QA_B + QB_B + offB[ks]);
            #pragma unroll
            for (int nt = 0; nt < 2; nt++)
                #pragma unroll
                for (int mt = 0; mt < 4; mt++) {
                    mma_f16(acc[mt][nt], ah[mt], bh + 2 * nt);
                    mma_f16(acc[mt][nt], ah[mt], bl + 2 * nt);
                }
        }
    };

    const int NKT = K / 64;   // 32
    cp_stage(0, 0);
    cp_stage(1, 1);
    int sc = 0, s2 = 2;
    for (int kt = 0; kt < NKT; kt++) {
        if (kt + 1 < NKT) { CP_WAIT(1); } else { CP_WAIT(0); }
        __syncthreads();
        if (kt + 2 < NKT) cp_stage(s2, kt + 2);
        compute(sc);
        if (++sc == 3) sc = 0;
        if (++s2 == 3) s2 = 0;
    }

    #pragma unroll
    for (int mt = 0; mt < 4; mt++)
        #pragma unroll
        for (int nt = 0; nt < 2; nt++) {
            const int r0 = bm + wm * 64 + mt * 16 + (lane >> 2);
            const int c0 = bn + wn * 16 + nt * 8 + (lane & 3) * 2;
            const float* d = acc[mt][nt];
            #pragma unroll
            for (int hrow = 0; hrow < 2; hrow++) {
                float v0 = fmaxf(d[hrow * 2 + 0], 0.f);
                float v1 = fmaxf(d[hrow * 2 + 1], 0.f);
                int rr = r0 + hrow * 8;
                if (OUT_SPLIT) {
                    __half h0, l0, h1, l1;
                    split16(v0, h0, l0);
                    split16(v1, h1, l1);
                    *(__half2*)(Xhi + (size_t)rr * E_DIM + c0) =
                        __halves2half2(h0, h1);
                    *(__half2*)(Xlo + (size_t)rr * E_DIM + c0) =
                        __halves2half2(l0, l1);
                } else {
                    *(float2*)(C + (size_t)rr * E_DIM + c0) =
                        make_float2(v0, v1);
                }
            }
        }
}

// ===========================================================================
// Launch
// ===========================================================================
extern "C" void kernel_launch(void* const* d_in, const int* in_sizes, int n_in,
                              void* d_out, int out_size)
{
    const float* Lemb = (const float*)d_in[0];
    const float* Xpt  = (const float*)d_in[1];
    const float* Wpt  = (const float*)d_in[2];
    const float* W0   = (const float*)d_in[3];
    const float* W1   = (const float*)d_in[4];
    float* out = (float*)d_out;

    float *S, *invs;
    __half *Zh, *Phi, *Ahi, *Alo, *Whi, *Wlo, *Thi, *Tlo;
    cudaGetSymbolAddress((void**)&Zh,   g_Zh);
    cudaGetSymbolAddress((void**)&invs, g_inv);
    cudaGetSymbolAddress((void**)&S,    g_S);
    cudaGetSymbolAddress((void**)&Phi,  g_Phi);
    cudaGetSymbolAddress((void**)&Ahi,  g_Ahi);
    cudaGetSymbolAddress((void**)&Alo,  g_Alo);
    cudaGetSymbolAddress((void**)&Whi,  g_Whi);
    cudaGetSymbolAddress((void**)&Wlo,  g_Wlo);
    cudaGetSymbolAddress((void**)&Thi,  g_Thi);
    cudaGetSymbolAddress((void**)&Tlo,  g_Tlo);

    cudaFuncSetAttribute(zzt_mma, cudaFuncAttributeMaxDynamicSharedMemorySize,
                         ZZT_SMEM);
    cudaFuncSetAttribute(split_mma, cudaFuncAttributeMaxDynamicSharedMemorySize,
                         SPLIT_SMEM);
    cudaFuncSetAttribute(gcn_mma<0>, cudaFuncAttributeMaxDynamicSharedMemorySize,
                         GCN_SMEM);
    cudaFuncSetAttribute(gcn_mma<1>, cudaFuncAttributeMaxDynamicSharedMemorySize,
                         GCN_SMEM);

    // 1) Zh fp16 + inv norms (+ g_cnt reset)
    compute_z<<<L_DIM, 512>>>(Xpt, Wpt, Zh, invs);

    // 2) scores = Z Z^T (single-pass fp16 mma), band scan fused
    zzt_mma<<<dim3(16, 16), 256, ZZT_SMEM>>>(Zh, S);

    // 3) exact fp32 fixup, recomputed from raw inputs
    fixup_band<<<1024, 128>>>(Xpt, Wpt, invs, S);

    // 4) adj = softmax(threshold(scores)) -> fp16 hi only
    masked_softmax<<<L_DIM, 256>>>(S, Phi);

    // 5) input conversions
    split_rows<<<(L_DIM * E_DIM + 255) / 256, 256>>>(Lemb, Ahi, Alo,
                                                     L_DIM * E_DIM);
    conv_wt2<<<dim3(16, 16, 2), 256>>>(W0, W1, Whi, Wlo);

    // 6) T0t = (Lemb @ W0)^T fp16 hi/lo
    split_mma<<<dim3(E_DIM / 64, L_DIM / 128), 256, SPLIT_SMEM>>>(
        Ahi, Alo, Whi, Wlo, Thi, Tlo);

    // 7) X1 = relu(adj @ T0) 2-pass -> fp16 hi/lo (overwrites Ahi/Alo)
    gcn_mma<1><<<dim3(E_DIM / 64, L_DIM / 128), 256, GCN_SMEM>>>(
        Phi, Thi, Tlo, nullptr, Ahi, Alo);

    // 8) T1t = (X1 @ W1)^T fp16 hi/lo
    split_mma<<<dim3(E_DIM / 64, L_DIM / 128), 256, SPLIT_SMEM>>>(
        Ahi, Alo, Whi + (size_t)E_DIM * E_DIM, Wlo + (size_t)E_DIM * E_DIM,
        Thi, Tlo);

    // 9) out = relu(adj @ T1) 2-pass fp32
    gcn_mma<0><<<dim3(E_DIM / 64, L_DIM / 128), 256, GCN_SMEM>>>(
        Phi, Thi, Tlo, out, nullptr, nullptr);
}

// round 12
// speedup vs baseline: 1.4266x; 1.1182x over previous
#include <cuda_runtime.h>
#include <cuda_fp16.h>
#include <math.h>
#include <stdint.h>

// Problem constants
#define L_DIM   2048
#define E_DIM   512
#define EPT_DIM 300
#define H_DIM   16
#define KBIG    (H_DIM * EPT_DIM)   // 4800

// Scratch (allocation-free rule: __device__ globals)
__device__ __half g_Zh [L_DIM * KBIG];   // fp16 Z (zzt input)
__device__ float  g_inv[L_DIM * H_DIM];  // per-(l,h) 0.25/norm
__device__ float  g_S  [L_DIM * L_DIM];  // scores
__device__ __half g_Phi[L_DIM * L_DIM];  // adj hi
__device__ __half g_Ahi[L_DIM * E_DIM];  // Lemb / X1 splits
__device__ __half g_Alo[L_DIM * E_DIM];
__device__ __half g_Whi[2 * E_DIM * E_DIM]; // W0^T, W1^T hi
__device__ __half g_Wlo[2 * E_DIM * E_DIM]; // W0^T, W1^T lo
__device__ __half g_Thi[E_DIM * L_DIM];  // T^T hi (B operand of gcn)

#define MAXB (1 << 18)
#define BANDW 1e-4f
__device__ int  g_cnt;
__device__ int2 g_list[MAXB];

// ===========================================================================
// Helpers
// ===========================================================================
__device__ __forceinline__ uint32_t smem_u32(const void* p) {
    uint32_t a;
    asm("{ .reg .u64 t; cvta.to.shared.u64 t, %1; cvt.u32.u64 %0, t; }"
        : "=r"(a) : "l"(p));
    return a;
}
__device__ __forceinline__ void ldsm_x4(uint32_t* r, uint32_t addr) {
    asm volatile("ldmatrix.sync.aligned.m8n8.x4.shared.b16 {%0,%1,%2,%3}, [%4];"
                 : "=r"(r[0]), "=r"(r[1]), "=r"(r[2]), "=r"(r[3]) : "r"(addr));
}
__device__ __forceinline__ void mma_f16(float* d, const uint32_t* a,
                                        const uint32_t* b) {
    asm volatile("mma.sync.aligned.m16n8k16.row.col.f32.f16.f16.f32 "
                 "{%0,%1,%2,%3}, {%4,%5,%6,%7}, {%8,%9}, {%0,%1,%2,%3};"
                 : "+f"(d[0]), "+f"(d[1]), "+f"(d[2]), "+f"(d[3])
                 : "r"(a[0]), "r"(a[1]), "r"(a[2]), "r"(a[3]),
                   "r"(b[0]), "r"(b[1]));
}
#define CP_ASYNC16(dst, src) \
    asm volatile("cp.async.cg.shared.global [%0], [%1], 16;" \
                 :: "r"(dst), "l"(src))
#define CP_COMMIT()  asm volatile("cp.async.commit_group;" ::: "memory")
#define CP_WAIT(N)   asm volatile("cp.async.wait_group " #N ";" ::: "memory")

__device__ __forceinline__ void split16(float v, __half& hi, __half& lo) {
    hi = __float2half_rn(v);
    lo = __float2half_rn(v - __half2float(hi));
}

// ===========================================================================
// Kernel 1: Zh (fp16, half2 stores) + inv norms. Warp per (l, h).
// ===========================================================================
__global__ __launch_bounds__(512) void compute_z(
    const float* __restrict__ xpt, const float* __restrict__ Wpt,
    __half* __restrict__ Zh, float* __restrict__ invs)
{
    const int l    = blockIdx.x;
    const int h    = threadIdx.x >> 5;
    const int lane = threadIdx.x & 31;
    if (l == 0 && threadIdx.x == 0) g_cnt = 0;

    const float* xrow = xpt + (size_t)l * EPT_DIM;
    const float* wrow = Wpt + h * EPT_DIM;

    float v0[5], v1[5];
    float ss = 0.f;
    #pragma unroll
    for (int i = 0; i < 5; i++) {
        int p = lane + i * 32;          // pair index, need p < 150
        float a = 0.f, b = 0.f;
        if (p < EPT_DIM / 2) {
            int e = 2 * p;
            float w0 = wrow[e],     w1 = wrow[e + 1];
            a = xrow[e] * w0 * w0;
            b = xrow[e + 1] * w1 * w1;
        }
        v0[i] = a; v1[i] = b;
        ss += a * a + b * b;
    }
    #pragma unroll
    for (int o = 16; o; o >>= 1) ss += __shfl_xor_sync(0xffffffffu, ss, o);
    float inv = 0.25f / fmaxf(sqrtf(ss), 1e-12f);
    if (lane == 0) invs[l * H_DIM + h] = inv;

    size_t base = (size_t)l * KBIG + h * EPT_DIM;
    #pragma unroll
    for (int i = 0; i < 5; i++) {
        int p = lane + i * 32;
        if (p < EPT_DIM / 2) {
            __half2 hv = __halves2half2(__float2half_rn(v0[i] * inv),
                                        __float2half_rn(v1[i] * inv));
            *(__half2*)(Zh + base + 2 * p) = hv;
        }
    }
}

// ===========================================================================
// Kernel 2: ZZ^T single-pass fp16 mma.sync; 3-stage cp.async; symmetric.
// ===========================================================================
#define TILE_B   16384
#define STAGE_B  (2 * TILE_B)
#define ZZT_SMEM (3 * STAGE_B + 128)

__global__ void __launch_bounds__(256, 1) zzt_mma(
    const __half* __restrict__ Zh, float* __restrict__ S)
{
    const int bx = blockIdx.x, by = blockIdx.y;
    if (bx < by) return;
    extern __shared__ char smem_raw[];
    const uint32_t sb = (smem_u32(smem_raw) + 127u) & ~127u;

    const int tid  = threadIdx.x;
    const int wid  = tid >> 5, lane = tid & 31;
    const int bm = by << 7, bn = bx << 7;
    const int wm = wid >> 2, wn = wid & 3;

    float acc[4][4][4];
    #pragma unroll
    for (int mt = 0; mt < 4; mt++)
        #pragma unroll
        for (int nt = 0; nt < 4; nt++)
            #pragma unroll
            for (int f = 0; f < 4; f++) acc[mt][nt][f] = 0.f;

    uint32_t offA[4][4], offBp[2][4];
    #pragma unroll
    for (int mt = 0; mt < 4; mt++) {
        int r  = wm * 64 + mt * 16 + (lane & 15);
        int r7 = r & 7;
        #pragma unroll
        for (int ks = 0; ks < 4; ks++) {
            int ch = ks * 2 + (lane >> 4);
            offA[mt][ks] = r * 128 + ((ch ^ r7) << 4);
        }
    }
    #pragma unroll
    for (int p = 0; p < 2; p++) {
        int ntl = p * 2 + ((lane >> 4) & 1);
        int r   = wn * 32 + ntl * 8 + (lane & 7);
        int r7  = r & 7;
        #pragma unroll
        for (int ks = 0; ks < 4; ks++) {
            int ch = ks * 2 + ((lane >> 3) & 1);
            offBp[p][ks] = r * 128 + ((ch ^ r7) << 4);
        }
    }

    uint32_t dstoff[4];
    int      srcA[4], srcB[4];
    #pragma unroll
    for (int t = 0; t < 4; t++) {
        int idx = tid + t * 256;
        int r = idx >> 3, ch = idx & 7;
        dstoff[t] = (uint32_t)(r * 128 + ((ch ^ (r & 7)) << 4));
        srcA[t] = (bm + r) * KBIG + ch * 8;
        srcB[t] = (bn + r) * KBIG + ch * 8;
    }

    auto cp_stage = [&](int s, int kt) {
        const int k0 = kt << 6;
        const uint32_t base = sb + (uint32_t)s * STAGE_B;
        #pragma unroll
        for (int t = 0; t < 4; t++) {
            CP_ASYNC16(base + dstoff[t],          Zh + srcA[t] + k0);
            CP_ASYNC16(base + TILE_B + dstoff[t], Zh + srcB[t] + k0);
        }
        CP_COMMIT();
    };

    auto compute = [&](int s) {
        const uint32_t pa = sb + (uint32_t)s * STAGE_B;
        #pragma unroll
        for (int ks = 0; ks < 4; ks++) {
            uint32_t ah[4][4];
            #pragma unroll
            for (int mt = 0; mt < 4; mt++)
                ldsm_x4(ah[mt], pa + offA[mt][ks]);
            #pragma unroll
            for (int p = 0; p < 2; p++) {
                uint32_t bh[4];
                ldsm_x4(bh, pa + TILE_B + offBp[p][ks]);
                #pragma unroll
                for (int half = 0; half < 2; half++) {
                    int nt = p * 2 + half;
                    #pragma unroll
                    for (int mt = 0; mt < 4; mt++)
                        mma_f16(acc[mt][nt], ah[mt], bh + 2 * half);
                }
            }
        }
    };

    const int NKT = KBIG / 64;   // 75
    cp_stage(0, 0);
    cp_stage(1, 1);
    int sc = 0, s2 = 2;
    for (int kt = 0; kt < NKT; kt++) {
        if (kt + 1 < NKT) { CP_WAIT(1); } else { CP_WAIT(0); }
        __syncthreads();
        if (kt + 2 < NKT) cp_stage(s2, kt + 2);
        compute(sc);
        if (++sc == 3) sc = 0;
        if (++s2 == 3) s2 = 0;
    }

    #pragma unroll
    for (int mt = 0; mt < 4; mt++)
        #pragma unroll
        for (int nt = 0; nt < 4; nt++) {
            const int r0 = bm + wm * 64 + mt * 16 + (lane >> 2);
            const int c0 = bn + wn * 32 + nt * 8 + (lane & 3) * 2;
            const float* d = acc[mt][nt];
            *(float2*)(S + (size_t)r0 * L_DIM + c0)       = make_float2(d[0], d[1]);
            *(float2*)(S + (size_t)(r0 + 8) * L_DIM + c0) = make_float2(d[2], d[3]);
            if (bx != by) {
                S[(size_t)c0 * L_DIM + r0]           = d[0];
                S[(size_t)(c0 + 1) * L_DIM + r0]     = d[1];
                S[(size_t)c0 * L_DIM + r0 + 8]       = d[2];
                S[(size_t)(c0 + 1) * L_DIM + r0 + 8] = d[3];
            }
            #pragma unroll
            for (int f = 0; f < 4; f++) {
                if (fabsf(d[f] - 0.1f) < BANDW) {
                    int rr = r0 + (f >> 1) * 8;
                    int cc = c0 + (f & 1);
                    int p = atomicAdd(&g_cnt, 1);
                    if (p < MAXB) g_list[p] = make_int2(rr, cc);
                    if (bx != by) {
                        p = atomicAdd(&g_cnt, 1);
                        if (p < MAXB) g_list[p] = make_int2(cc, rr);
                    }
                }
            }
        }
}

// ===========================================================================
// Fixup: exact fp32 recompute from raw inputs.
// ===========================================================================
__global__ __launch_bounds__(128) void fixup_band(
    const float* __restrict__ xpt, const float* __restrict__ Wpt,
    const float* __restrict__ invs, float* __restrict__ S)
{
    __shared__ float sxi[EPT_DIM], sxj[EPT_DIM];
    __shared__ float hred[H_DIM];
    const int tid = threadIdx.x;
    const int h   = tid >> 3;
    const int sub = tid & 7;
    int cnt = g_cnt; if (cnt > MAXB) cnt = MAXB;

    for (int e = blockIdx.x; e < cnt; e += gridDim.x) {
        int2 ij = g_list[e];
        for (int k = tid; k < EPT_DIM; k += 128) {
            sxi[k] = xpt[(size_t)ij.x * EPT_DIM + k];
            sxj[k] = xpt[(size_t)ij.y * EPT_DIM + k];
        }
        __syncthreads();

        const float* wrow = Wpt + h * EPT_DIM;
        float d = 0.f;
        for (int k = sub; k < EPT_DIM; k += 8) {
            float w = __ldg(wrow + k);
            float w2 = w * w;
            float a = sxi[k] * w2;
            float b = sxj[k] * w2;
            d = fmaf(a, b, d);
        }
        d += __shfl_xor_sync(0xffffffffu, d, 4);
        d += __shfl_xor_sync(0xffffffffu, d, 2);
        d += __shfl_xor_sync(0xffffffffu, d, 1);
        if (sub == 0)
            hred[h] = d * invs[ij.x * H_DIM + h] * invs[ij.y * H_DIM + h];
        __syncthreads();
        if (tid == 0) {
            float s = 0.f;
            #pragma unroll
            for (int hh = 0; hh < H_DIM; hh++) s += hred[hh];
            S[(size_t)ij.x * L_DIM + ij.y] = s;
        }
        __syncthreads();
    }
}

// ===========================================================================
// Masked softmax -> adj fp16 (hi only)
// ===========================================================================
__global__ __launch_bounds__(256) void masked_softmax(
    const float* __restrict__ S, __half* __restrict__ Phi)
{
    __shared__ float red[8];
    const int r   = blockIdx.x;
    const int tid = threadIdx.x;
    const float* row = S + (size_t)r * L_DIM;

    float v[8];
    #pragma unroll
    for (int i = 0; i < 8; i++) v[i] = row[tid + i * 256];

    float m = -1e30f;
    #pragma unroll
    for (int i = 0; i < 8; i++)
        if (v[i] >= 0.1f) m = fmaxf(m, v[i]);
    #pragma unroll
    for (int o = 16; o; o >>= 1) m = fmaxf(m, __shfl_xor_sync(0xffffffffu, m, o));
    if ((tid & 31) == 0) red[tid >> 5] = m;
    __syncthreads();
    float M = fmaxf(fmaxf(fmaxf(red[0], red[1]), fmaxf(red[2], red[3])),
                    fmaxf(fmaxf(red[4], red[5]), fmaxf(red[6], red[7])));
    __syncthreads();

    float sum = 0.f;
    #pragma unroll
    for (int i = 0; i < 8; i++) {
        v[i] = (v[i] >= 0.1f) ? expf(v[i] - M) : 0.f;
        sum += v[i];
    }
    #pragma unroll
    for (int o = 16; o; o >>= 1) sum += __shfl_xor_sync(0xffffffffu, sum, o);
    if ((tid & 31) == 0) red[tid >> 5] = sum;
    __syncthreads();
    float T = red[0] + red[1] + red[2] + red[3] +
              red[4] + red[5] + red[6] + red[7];
    float inv = 1.f / T;

    #pragma unroll
    for (int i = 0; i < 8; i++)
        Phi[(size_t)r * L_DIM + tid + i * 256] = __float2half_rn(v[i] * inv);
}

// ===========================================================================
// prep: merged Lemb row-split + both weight transpose-splits.
// Blocks [0, 4096): split_rows; blocks [4096, 4608): conv_wt (z = b>>8).
// ===========================================================================
#define NB_SPLIT (L_DIM * E_DIM / 256)   // 4096

__global__ __launch_bounds__(256) void prep(
    const float* __restrict__ Lemb,
    const float* __restrict__ W0, const float* __restrict__ W1,
    __half* __restrict__ Ahi, __half* __restrict__ Alo,
    __half* __restrict__ Whi, __half* __restrict__ Wlo)
{
    __shared__ float t[32][33];
    if ((int)blockIdx.x < NB_SPLIT) {
        int i = blockIdx.x * 256 + threadIdx.x;
        __half hb, lb;
        split16(Lemb[i], hb, lb);
        Ahi[i] = hb; Alo[i] = lb;
    } else {
        int b = blockIdx.x - NB_SPLIT;            // 0..511
        int z  = b >> 8;                          // 0/1
        int by = ((b >> 4) & 15) * 32;
        int bx = (b & 15) * 32;
        const float* W = z ? W1 : W0;
        __half* whi = Whi + (size_t)z * E_DIM * E_DIM;
        __half* wlo = Wlo + (size_t)z * E_DIM * E_DIM;
        const int x = threadIdx.x & 31, y4 = (threadIdx.x >> 5) * 4;
        #pragma unroll
        for (int i = 0; i < 4; i++)
            t[y4 + i][x] = W[(size_t)(by + y4 + i) * E_DIM + bx + x];
        __syncthreads();
        #pragma unroll
        for (int i = 0; i < 4; i++) {
            float v = t[x][y4 + i];
            __half hb, lb;
            split16(v, hb, lb);
            size_t o = (size_t)(bx + y4 + i) * E_DIM + by + x;
            whi[o] = hb; wlo[o] = lb;
        }
    }
}

// ===========================================================================
// split_mma: T = A @ W (3-pass fp16 internally), writes T^T HI ONLY [512,2048].
// ===========================================================================
#define GA_B 16384
#define GB_B 8192
#define GSTAGE_B (2 * GA_B + 2 * GB_B)
#define SPLIT_SMEM (3 * GSTAGE_B + 128)

__global__ void __launch_bounds__(256, 1) split_mma(
    const __half* __restrict__ Ahi, const __half* __restrict__ Alo,
    const __half* __restrict__ Bhi, const __half* __restrict__ Blo,
    __half* __restrict__ Thi)
{
    const int K = E_DIM;   // 512
    extern __shared__ char smem_raw[];
    const uint32_t sb = (smem_u32(smem_raw) + 127u) & ~127u;

    const int tid  = threadIdx.x;
    const int wid  = tid >> 5, lane = tid & 31;
    const int bm = blockIdx.y << 7;
    const int bn = blockIdx.x << 6;
    const int wm = wid >> 2, wn = wid & 3;

    float acc[4][2][4];
    #pragma unroll
    for (int mt = 0; mt < 4; mt++)
        #pragma unroll
        for (int nt = 0; nt < 2; nt++)
            #pragma unroll
            for (int f = 0; f < 4; f++) acc[mt][nt][f] = 0.f;

    uint32_t offA[4][4], offB[4];
    #pragma unroll
    for (int mt = 0; mt < 4; mt++) {
        int r  = wm * 64 + mt * 16 + (lane & 15);
        int r7 = r & 7;
        #pragma unroll
        for (int ks = 0; ks < 4; ks++) {
            int ch = ks * 2 + (lane >> 4);
            offA[mt][ks] = r * 128 + ((ch ^ r7) << 4);
        }
    }
    {
        int ntl = (lane >> 4) & 1;
        int r   = wn * 16 + ntl * 8 + (lane & 7);
        int r7  = r & 7;
        #pragma unroll
        for (int ks = 0; ks < 4; ks++) {
            int ch = ks * 2 + ((lane >> 3) & 1);
            offB[ks] = r * 128 + ((ch ^ r7) << 4);
        }
    }

    uint32_t dstA[4]; int srcA[4];
    #pragma unroll
    for (int t = 0; t < 4; t++) {
        int idx = tid + t * 256;
        int r = idx >> 3, ch = idx & 7;
        dstA[t] = (uint32_t)(r * 128 + ((ch ^ (r & 7)) << 4));
        srcA[t] = (bm + r) * K + ch * 8;
    }
    uint32_t dstB[2]; int srcB[2];
    #pragma unroll
    for (int t = 0; t < 2; t++) {
        int idx = tid + t * 256;
        int r = idx >> 3, ch = idx & 7;
        dstB[t] = (uint32_t)(r * 128 + ((ch ^ (r & 7)) << 4));
        srcB[t] = (bn + r) * K + ch * 8;
    }

    auto cp_stage = [&](int s, int kt) {
        const int k0 = kt << 6;
        const uint32_t base = sb + (uint32_t)s * GSTAGE_B;
        #pragma unroll
        for (int t = 0; t < 4; t++) {
            CP_ASYNC16(base + dstA[t],        Ahi + srcA[t] + k0);
            CP_ASYNC16(base + GA_B + dstA[t], Alo + srcA[t] + k0);
        }
        #pragma unroll
        for (int t = 0; t < 2; t++) {
            CP_ASYNC16(base + 2 * GA_B + dstB[t],        Bhi + srcB[t] + k0);
            CP_ASYNC16(base + 2 * GA_B + GB_B + dstB[t], Blo + srcB[t] + k0);
        }
        CP_COMMIT();
    };

    auto compute = [&](int s) {
        const uint32_t pa = sb + (uint32_t)s * GSTAGE_B;
        #pragma unroll
        for (int ks = 0; ks < 4; ks++) {
            uint32_t ahi[4][4], alo[4][4], bh[4], bl[4];
            #pragma unroll
            for (int mt = 0; mt < 4; mt++) {
                ldsm_x4(ahi[mt], pa + offA[mt][ks]);
                ldsm_x4(alo[mt], pa + GA_B + offA[mt][ks]);
            }
            ldsm_x4(bh, pa + 2 * GA_B + offB[ks]);
            ldsm_x4(bl, pa + 2 * GA_B + GB_B + offB[ks]);
            #pragma unroll
            for (int nt = 0; nt < 2; nt++)
                #pragma unroll
                for (int mt = 0; mt < 4; mt++) {
                    mma_f16(acc[mt][nt], ahi[mt], bh + 2 * nt);
                    mma_f16(acc[mt][nt], ahi[mt], bl + 2 * nt);
                    mma_f16(acc[mt][nt], alo[mt], bh + 2 * nt);
                }
        }
    };

    const int NKT = K / 64;   // 8
    cp_stage(0, 0);
    cp_stage(1, 1);
    int sc = 0, s2 = 2;
    for (int kt = 0; kt < NKT; kt++) {
        if (kt + 1 < NKT) { CP_WAIT(1); } else { CP_WAIT(0); }
        __syncthreads();
        if (kt + 2 < NKT) cp_stage(s2, kt + 2);
        compute(sc);
        if (++sc == 3) sc = 0;
        if (++s2 == 3) s2 = 0;
    }

    // transposed HI-only epilogue: Tt[n][m]
    #pragma unroll
    for (int mt = 0; mt < 4; mt++)
        #pragma unroll
        for (int nt = 0; nt < 2; nt++) {
            const int r0 = bm + wm * 64 + mt * 16 + (lane >> 2);
            const int c0 = bn + wn * 16 + nt * 8 + (lane & 3) * 2;
            const float* d = acc[mt][nt];
            #pragma unroll
            for (int f = 0; f < 4; f++) {
                int rr = r0 + (f >> 1) * 8;
                int cc = c0 + (f & 1);
                Thi[(size_t)cc * L_DIM + rr] = __float2half_rn(d[f]);
            }
        }
}

// ===========================================================================
// gcn_mma: C = relu(P_hi @ T_hi^T), 1-pass fp16.
// OUT_SPLIT=1 -> fp16 hi/lo row-major (X1); OUT_SPLIT=0 -> fp32 out.
// ===========================================================================
#define QA_B 16384                  // P hi tile: 128 x 128B
#define QB_B 8192                   // T hi tile: 64 x 128B
#define QSTAGE_B (QA_B + QB_B)      // 24 KB
#define GCN_SMEM (3 * QSTAGE_B + 128)

template <int OUT_SPLIT>
__global__ void __launch_bounds__(256, 1) gcn_mma(
    const __half* __restrict__ Ph, const __half* __restrict__ Bh,
    float* __restrict__ C, __half* __restrict__ Xhi, __half* __restrict__ Xlo)
{
    const int K = L_DIM;   // 2048
    extern __shared__ char smem_raw[];
    const uint32_t sb = (smem_u32(smem_raw) + 127u) & ~127u;

    const int tid  = threadIdx.x;
    const int wid  = tid >> 5, lane = tid & 31;
    const int bm = blockIdx.y << 7;
    const int bn = blockIdx.x << 6;
    const int wm = wid >> 2, wn = wid & 3;

    float acc[4][2][4];
    #pragma unroll
    for (int mt = 0; mt < 4; mt++)
        #pragma unroll
        for (int nt = 0; nt < 2; nt++)
            #pragma unroll
            for (int f = 0; f < 4; f++) acc[mt][nt][f] = 0.f;

    uint32_t offA[4][4], offB[4];
    #pragma unroll
    for (int mt = 0; mt < 4; mt++) {
        int r  = wm * 64 + mt * 16 + (lane & 15);
        int r7 = r & 7;
        #pragma unroll
        for (int ks = 0; ks < 4; ks++) {
            int ch = ks * 2 + (lane >> 4);
            offA[mt][ks] = r * 128 + ((ch ^ r7) << 4);
        }
    }
    {
        int ntl = (lane >> 4) & 1;
        int r   = wn * 16 + ntl * 8 + (lane & 7);
        int r7  = r & 7;
        #pragma unroll
        for (int ks = 0; ks < 4; ks++) {
            int ch = ks * 2 + ((lane >> 3) & 1);
            offB[ks] = r * 128 + ((ch ^ r7) << 4);
        }
    }

    uint32_t dstA[4]; int srcA[4];
    #pragma unroll
    for (int t = 0; t < 4; t++) {
        int idx = tid + t * 256;
        int r = idx >> 3, ch = idx & 7;
        dstA[t] = (uint32_t)(r * 128 + ((ch ^ (r & 7)) << 4));
        srcA[t] = (bm + r) * K + ch * 8;
    }
    uint32_t dstB[2]; int srcB[2];
    #pragma unroll
    for (int t = 0; t < 2; t++) {
        int idx = tid + t * 256;
        int r = idx >> 3, ch = idx & 7;
        dstB[t] = (uint32_t)(r * 128 + ((ch ^ (r & 7)) << 4));
        srcB[t] = (bn + r) * K + ch * 8;
    }

    auto cp_stage = [&](int s, int kt) {
        const int k0 = kt << 6;
        const uint32_t base = sb + (uint32_t)s * QSTAGE_B;
        #pragma unroll
        for (int t = 0; t < 4; t++)
            CP_ASYNC16(base + dstA[t], Ph + srcA[t] + k0);
        #pragma unroll
        for (int t = 0; t < 2; t++)
            CP_ASYNC16(base + QA_B + dstB[t], Bh + srcB[t] + k0);
        CP_COMMIT();
    };

    auto compute = [&](int s) {
        const uint32_t pa = sb + (uint32_t)s * QSTAGE_B;
        #pragma unroll
        for (int ks = 0; ks < 4; ks++) {
            uint32_t ah[4][4], bh[4];
            #pragma unroll
            for (int mt = 0; mt < 4; mt++)
                ldsm_x4(ah[mt], pa + offA[mt][ks]);
            ldsm_x4(bh, pa + QA_B + offB[ks]);
            #pragma unroll
            for (int nt = 0; nt < 2; nt++)
                #pragma unroll
                for (int mt = 0; mt < 4; mt++)
                    mma_f16(acc[mt][nt], ah[mt], bh + 2 * nt);
        }
    };

    const int NKT = K / 64;   // 32
    cp_stage(0, 0);
    cp_stage(1, 1);
    int sc = 0, s2 = 2;
    for (int kt = 0; kt < NKT; kt++) {
        if (kt + 1 < NKT) { CP_WAIT(1); } else { CP_WAIT(0); }
        __syncthreads();
        if (kt + 2 < NKT) cp_stage(s2, kt + 2);
        compute(sc);
        if (++sc == 3) sc = 0;
        if (++s2 == 3) s2 = 0;
    }

    #pragma unroll
    for (int mt = 0; mt < 4; mt++)
        #pragma unroll
        for (int nt = 0; nt < 2; nt++) {
            const int r0 = bm + wm * 64 + mt * 16 + (lane >> 2);
            const int c0 = bn + wn * 16 + nt * 8 + (lane & 3) * 2;
            const float* d = acc[mt][nt];
            #pragma unroll
            for (int hrow = 0; hrow < 2; hrow++) {
                float v0 = fmaxf(d[hrow * 2 + 0], 0.f);
                float v1 = fmaxf(d[hrow * 2 + 1], 0.f);
                int rr = r0 + hrow * 8;
                if (OUT_SPLIT) {
                    __half h0, l0, h1, l1;
                    split16(v0, h0, l0);
                    split16(v1, h1, l1);
                    *(__half2*)(Xhi + (size_t)rr * E_DIM + c0) =
                        __halves2half2(h0, h1);
                    *(__half2*)(Xlo + (size_t)rr * E_DIM + c0) =
                        __halves2half2(l0, l1);
                } else {
                    *(float2*)(C + (size_t)rr * E_DIM + c0) =
                        make_float2(v0, v1);
                }
            }
        }
}

// ===========================================================================
// Launch
// ===========================================================================
extern "C" void kernel_launch(void* const* d_in, const int* in_sizes, int n_in,
                              void* d_out, int out_size)
{
    const float* Lemb = (const float*)d_in[0];
    const float* Xpt  = (const float*)d_in[1];
    const float* Wpt  = (const float*)d_in[2];
    const float* W0   = (const float*)d_in[3];
    const float* W1   = (const float*)d_in[4];
    float* out = (float*)d_out;

    float *S, *invs;
    __half *Zh, *Phi, *Ahi, *Alo, *Whi, *Wlo, *Thi;
    cudaGetSymbolAddress((void**)&Zh,   g_Zh);
    cudaGetSymbolAddress((void**)&invs, g_inv);
    cudaGetSymbolAddress((void**)&S,    g_S);
    cudaGetSymbolAddress((void**)&Phi,  g_Phi);
    cudaGetSymbolAddress((void**)&Ahi,  g_Ahi);
    cudaGetSymbolAddress((void**)&Alo,  g_Alo);
    cudaGetSymbolAddress((void**)&Whi,  g_Whi);
    cudaGetSymbolAddress((void**)&Wlo,  g_Wlo);
    cudaGetSymbolAddress((void**)&Thi,  g_Thi);

    cudaFuncSetAttribute(zzt_mma, cudaFuncAttributeMaxDynamicSharedMemorySize,
                         ZZT_SMEM);
    cudaFuncSetAttribute(split_mma, cudaFuncAttributeMaxDynamicSharedMemorySize,
                         SPLIT_SMEM);
    cudaFuncSetAttribute(gcn_mma<0>, cudaFuncAttributeMaxDynamicSharedMemorySize,
                         GCN_SMEM);
    cudaFuncSetAttribute(gcn_mma<1>, cudaFuncAttributeMaxDynamicSharedMemorySize,
                         GCN_SMEM);

    // 1) Zh fp16 + inv norms (+ g_cnt reset)
    compute_z<<<L_DIM, 512>>>(Xpt, Wpt, Zh, invs);

    // 2) scores = Z Z^T (single-pass fp16 mma), band scan fused
    zzt_mma<<<dim3(16, 16), 256, ZZT_SMEM>>>(Zh, S);

    // 3) exact fp32 fixup, recomputed from raw inputs
    fixup_band<<<1024, 128>>>(Xpt, Wpt, invs, S);

    // 4) adj = softmax(threshold(scores)) -> fp16 hi only
    masked_softmax<<<L_DIM, 256>>>(S, Phi);

    // 5) merged conversions (Lemb split + both weight transposes)
    prep<<<NB_SPLIT + 512, 256>>>(Lemb, W0, W1, Ahi, Alo, Whi, Wlo);

    // 6) T0t = (Lemb @ W0)^T fp16 hi
    split_mma<<<dim3(E_DIM / 64, L_DIM / 128), 256, SPLIT_SMEM>>>(
        Ahi, Alo, Whi, Wlo, Thi);

    // 7) X1 = relu(adj @ T0) 1-pass -> fp16 hi/lo (overwrites Ahi/Alo)
    gcn_mma<1><<<dim3(E_DIM / 64, L_DIM / 128), 256, GCN_SMEM>>>(
        Phi, Thi, nullptr, Ahi, Alo);

    // 8) T1t = (X1 @ W1)^T fp16 hi
    split_mma<<<dim3(E_DIM / 64, L_DIM / 128), 256, SPLIT_SMEM>>>(
        Ahi, Alo, Whi + (size_t)E_DIM * E_DIM, Wlo + (size_t)E_DIM * E_DIM,
        Thi);

    // 9) out = relu(adj @ T1) 1-pass fp32
    gcn_mma<0><<<dim3(E_DIM / 64, L_DIM / 128), 256, GCN_SMEM>>>(
        Phi, Thi, out, nullptr, nullptr);
}

// round 13
// speedup vs baseline: 1.5111x; 1.0593x over previous
#include <cuda_runtime.h>
#include <cuda_fp16.h>
#include <math.h>
#include <stdint.h>

// Problem constants
#define L_DIM   2048
#define E_DIM   512
#define EPT_DIM 300
#define H_DIM   16
#define KBIG    (H_DIM * EPT_DIM)   // 4800

#define BANDW 1e-4f

// Scratch (allocation-free rule: __device__ globals)
__device__ __half g_Zh [L_DIM * KBIG];   // fp16 Z (zzt input)
__device__ float  g_inv[L_DIM * H_DIM];  // per-(l,h) 0.25/norm
__device__ float  g_S  [L_DIM * L_DIM];  // scores
__device__ __half g_Phi[L_DIM * L_DIM];  // adj fp16
__device__ __half g_Ah [L_DIM * E_DIM];  // Lemb / X1 fp16
__device__ __half g_Wt [2 * E_DIM * E_DIM]; // W0^T, W1^T fp16
__device__ __half g_Th [E_DIM * L_DIM];  // T^T fp16 (B operand of gcn)

// ===========================================================================
// Helpers
// ===========================================================================
__device__ __forceinline__ uint32_t smem_u32(const void* p) {
    uint32_t a;
    asm("{ .reg .u64 t; cvta.to.shared.u64 t, %1; cvt.u32.u64 %0, t; }"
        : "=r"(a) : "l"(p));
    return a;
}
__device__ __forceinline__ void ldsm_x4(uint32_t* r, uint32_t addr) {
    asm volatile("ldmatrix.sync.aligned.m8n8.x4.shared.b16 {%0,%1,%2,%3}, [%4];"
                 : "=r"(r[0]), "=r"(r[1]), "=r"(r[2]), "=r"(r[3]) : "r"(addr));
}
__device__ __forceinline__ void mma_f16(float* d, const uint32_t* a,
                                        const uint32_t* b) {
    asm volatile("mma.sync.aligned.m16n8k16.row.col.f32.f16.f16.f32 "
                 "{%0,%1,%2,%3}, {%4,%5,%6,%7}, {%8,%9}, {%0,%1,%2,%3};"
                 : "+f"(d[0]), "+f"(d[1]), "+f"(d[2]), "+f"(d[3])
                 : "r"(a[0]), "r"(a[1]), "r"(a[2]), "r"(a[3]),
                   "r"(b[0]), "r"(b[1]));
}
#define CP_ASYNC16(dst, src) \
    asm volatile("cp.async.cg.shared.global [%0], [%1], 16;" \
                 :: "r"(dst), "l"(src))
#define CP_COMMIT()  asm volatile("cp.async.commit_group;" ::: "memory")
#define CP_WAIT(N)   asm volatile("cp.async.wait_group " #N ";" ::: "memory")

// ===========================================================================
// Kernel 1: prep_all — compute_z + Lemb->fp16 + W0^T/W1^T->fp16, one launch.
// blocks [0, 2048):            compute_z, row = blockIdx.x (16 warps x 1 head)
// blocks [2048, 2560):         Lemb convert (4 floats/thread)
// blocks [2560, 2816):         W transposes (2 x 32x32 tiles per block)
// ===========================================================================
#define PREP_ZB   L_DIM              // 2048
#define PREP_LB   512                // Lemb convert blocks
#define PREP_WB   256                // W transpose blocks
#define PREP_GRID (PREP_ZB + PREP_LB + PREP_WB)

__global__ __launch_bounds__(512) void prep_all(
    const float* __restrict__ xpt, const float* __restrict__ Wpt,
    const float* __restrict__ Lemb,
    const float* __restrict__ W0, const float* __restrict__ W1,
    __half* __restrict__ Zh, float* __restrict__ invs,
    __half* __restrict__ Ah, __half* __restrict__ Wt)
{
    __shared__ float tbuf[2][32][33];
    const int blk = blockIdx.x;

    if (blk < PREP_ZB) {
        // ---- compute_z ----
        const int l    = blk;
        const int h    = threadIdx.x >> 5;
        const int lane = threadIdx.x & 31;
        const float* xrow = xpt + (size_t)l * EPT_DIM;
        const float* wrow = Wpt + h * EPT_DIM;

        float v0[5], v1[5];
        float ss = 0.f;
        #pragma unroll
        for (int i = 0; i < 5; i++) {
            int p = lane + i * 32;
            float a = 0.f, b = 0.f;
            if (p < EPT_DIM / 2) {
                int e = 2 * p;
                float w0 = wrow[e], w1 = wrow[e + 1];
                a = xrow[e] * w0 * w0;
                b = xrow[e + 1] * w1 * w1;
            }
            v0[i] = a; v1[i] = b;
            ss += a * a + b * b;
        }
        #pragma unroll
        for (int o = 16; o; o >>= 1) ss += __shfl_xor_sync(0xffffffffu, ss, o);
        float inv = 0.25f / fmaxf(sqrtf(ss), 1e-12f);
        if (lane == 0) invs[l * H_DIM + h] = inv;

        size_t base = (size_t)l * KBIG + h * EPT_DIM;
        #pragma unroll
        for (int i = 0; i < 5; i++) {
            int p = lane + i * 32;
            if (p < EPT_DIM / 2) {
                __half2 hv = __halves2half2(__float2half_rn(v0[i] * inv),
                                            __float2half_rn(v1[i] * inv));
                *(__half2*)(Zh + base + 2 * p) = hv;
            }
        }
    } else if (blk < PREP_ZB + PREP_LB) {
        // ---- Lemb -> fp16 (4 per thread) ----
        int i4 = ((blk - PREP_ZB) * 512 + threadIdx.x) * 4;
        float4 v = *(const float4*)(Lemb + i4);
        __half2 h0 = __halves2half2(__float2half_rn(v.x), __float2half_rn(v.y));
        __half2 h1 = __halves2half2(__float2half_rn(v.z), __float2half_rn(v.w));
        *(__half2*)(Ah + i4)     = h0;
        *(__half2*)(Ah + i4 + 2) = h1;
    } else {
        // ---- W transposes: 2 tiles per block ----
        int b    = blk - PREP_ZB - PREP_LB;      // 0..255
        int hf   = threadIdx.x >> 8;             // 0/1 -> tile within block
        int t256 = threadIdx.x & 255;
        int tile = b * 2 + hf;                   // 0..511
        int z    = tile >> 8;                    // 0: W0, 1: W1
        int rem  = tile & 255;
        int by   = (rem >> 4) * 32, bx = (rem & 15) * 32;
        const float* W = z ? W1 : W0;
        __half* wt = Wt + (size_t)z * E_DIM * E_DIM;
        const int x = t256 & 31, y4 = (t256 >> 5) * 4;
        #pragma unroll
        for (int i = 0; i < 4; i++)
            tbuf[hf][y4 + i][x] = W[(size_t)(by + y4 + i) * E_DIM + bx + x];
        __syncthreads();
        #pragma unroll
        for (int i = 0; i < 4; i++) {
            float v = tbuf[hf][x][y4 + i];       // W[by+x][bx+y4+i]
            wt[(size_t)(bx + y4 + i) * E_DIM + by + x] = __float2half_rn(v);
        }
    }
}

// ===========================================================================
// Kernel 2: ZZ^T single-pass fp16 mma.sync; 3-stage cp.async; symmetric.
// (band handling moved into softmax — no atomics here)
// ===========================================================================
#define TILE_B   16384
#define STAGE_B  (2 * TILE_B)
#define ZZT_SMEM (3 * STAGE_B + 128)

__global__ void __launch_bounds__(256, 1) zzt_mma(
    const __half* __restrict__ Zh, float* __restrict__ S)
{
    const int bx = blockIdx.x, by = blockIdx.y;
    if (bx < by) return;
    extern __shared__ char smem_raw[];
    const uint32_t sb = (smem_u32(smem_raw) + 127u) & ~127u;

    const int tid  = threadIdx.x;
    const int wid  = tid >> 5, lane = tid & 31;
    const int bm = by << 7, bn = bx << 7;
    const int wm = wid >> 2, wn = wid & 3;

    float acc[4][4][4];
    #pragma unroll
    for (int mt = 0; mt < 4; mt++)
        #pragma unroll
        for (int nt = 0; nt < 4; nt++)
            #pragma unroll
            for (int f = 0; f < 4; f++) acc[mt][nt][f] = 0.f;

    uint32_t offA[4][4], offBp[2][4];
    #pragma unroll
    for (int mt = 0; mt < 4; mt++) {
        int r  = wm * 64 + mt * 16 + (lane & 15);
        int r7 = r & 7;
        #pragma unroll
        for (int ks = 0; ks < 4; ks++) {
            int ch = ks * 2 + (lane >> 4);
            offA[mt][ks] = r * 128 + ((ch ^ r7) << 4);
        }
    }
    #pragma unroll
    for (int p = 0; p < 2; p++) {
        int ntl = p * 2 + ((lane >> 4) & 1);
        int r   = wn * 32 + ntl * 8 + (lane & 7);
        int r7  = r & 7;
        #pragma unroll
        for (int ks = 0; ks < 4; ks++) {
            int ch = ks * 2 + ((lane >> 3) & 1);
            offBp[p][ks] = r * 128 + ((ch ^ r7) << 4);
        }
    }

    uint32_t dstoff[4];
    int      srcA[4], srcB[4];
    #pragma unroll
    for (int t = 0; t < 4; t++) {
        int idx = tid + t * 256;
        int r = idx >> 3, ch = idx & 7;
        dstoff[t] = (uint32_t)(r * 128 + ((ch ^ (r & 7)) << 4));
        srcA[t] = (bm + r) * KBIG + ch * 8;
        srcB[t] = (bn + r) * KBIG + ch * 8;
    }

    auto cp_stage = [&](int s, int kt) {
        const int k0 = kt << 6;
        const uint32_t base = sb + (uint32_t)s * STAGE_B;
        #pragma unroll
        for (int t = 0; t < 4; t++) {
            CP_ASYNC16(base + dstoff[t],          Zh + srcA[t] + k0);
            CP_ASYNC16(base + TILE_B + dstoff[t], Zh + srcB[t] + k0);
        }
        CP_COMMIT();
    };

    auto compute = [&](int s) {
        const uint32_t pa = sb + (uint32_t)s * STAGE_B;
        #pragma unroll
        for (int ks = 0; ks < 4; ks++) {
            uint32_t ah[4][4];
            #pragma unroll
            for (int mt = 0; mt < 4; mt++)
                ldsm_x4(ah[mt], pa + offA[mt][ks]);
            #pragma unroll
            for (int p = 0; p < 2; p++) {
                uint32_t bh[4];
                ldsm_x4(bh, pa + TILE_B + offBp[p][ks]);
                #pragma unroll
                for (int half = 0; half < 2; half++) {
                    int nt = p * 2 + half;
                    #pragma unroll
                    for (int mt = 0; mt < 4; mt++)
                        mma_f16(acc[mt][nt], ah[mt], bh + 2 * half);
                }
            }
        }
    };

    const int NKT = KBIG / 64;   // 75
    cp_stage(0, 0);
    cp_stage(1, 1);
    int sc = 0, s2 = 2;
    for (int kt = 0; kt < NKT; kt++) {
        if (kt + 1 < NKT) { CP_WAIT(1); } else { CP_WAIT(0); }
        __syncthreads();
        if (kt + 2 < NKT) cp_stage(s2, kt + 2);
        compute(sc);
        if (++sc == 3) sc = 0;
        if (++s2 == 3) s2 = 0;
    }

    #pragma unroll
    for (int mt = 0; mt < 4; mt++)
        #pragma unroll
        for (int nt = 0; nt < 4; nt++) {
            const int r0 = bm + wm * 64 + mt * 16 + (lane >> 2);
            const int c0 = bn + wn * 32 + nt * 8 + (lane & 3) * 2;
            const float* d = acc[mt][nt];
            *(float2*)(S + (size_t)r0 * L_DIM + c0)       = make_float2(d[0], d[1]);
            *(float2*)(S + (size_t)(r0 + 8) * L_DIM + c0) = make_float2(d[2], d[3]);
            if (bx != by) {
                S[(size_t)c0 * L_DIM + r0]           = d[0];
                S[(size_t)(c0 + 1) * L_DIM + r0]     = d[1];
                S[(size_t)c0 * L_DIM + r0 + 8]       = d[2];
                S[(size_t)(c0 + 1) * L_DIM + r0 + 8] = d[3];
            }
        }
}

// ===========================================================================
// Kernel 3: masked softmax WITH inline exact fixup of near-threshold entries.
// One block per row. Band entries in this row are recomputed exactly (fp32,
// from raw inputs) by the whole block before threshold/softmax.
// ===========================================================================
#define MAXROWBAND 32

__global__ __launch_bounds__(256) void masked_softmax_fix(
    const float* __restrict__ S,
    const float* __restrict__ xpt, const float* __restrict__ Wpt,
    const float* __restrict__ invs, __half* __restrict__ Phi)
{
    __shared__ float red[8];
    __shared__ int   bcols[MAXROWBAND];
    __shared__ int   bcnt;
    __shared__ float ivp[H_DIM];
    __shared__ float exact_val;

    const int r   = blockIdx.x;
    const int tid = threadIdx.x;
    const float* row = S + (size_t)r * L_DIM;

    float v[8];
    #pragma unroll
    for (int i = 0; i < 8; i++) v[i] = row[tid + i * 256];

    if (tid == 0) bcnt = 0;
    __syncthreads();
    #pragma unroll
    for (int i = 0; i < 8; i++) {
        if (fabsf(v[i] - 0.1f) < BANDW) {
            int p = atomicAdd(&bcnt, 1);
            if (p < MAXROWBAND) bcols[p] = tid + i * 256;
        }
    }
    __syncthreads();

    int nb = bcnt; if (nb > MAXROWBAND) nb = MAXROWBAND;
    for (int b = 0; b < nb; b++) {
        int c = bcols[b];
        if (tid < H_DIM)
            ivp[tid] = invs[r * H_DIM + tid] * invs[c * H_DIM + tid];
        __syncthreads();
        const float* xr = xpt + (size_t)r * EPT_DIM;
        const float* xc = xpt + (size_t)c * EPT_DIM;
        float part = 0.f;
        for (int g = tid; g < KBIG; g += 256) {
            int h = g / EPT_DIM;
            int e = g - h * EPT_DIM;
            float w = Wpt[g];
            float w2 = w * w;
            part = fmaf((xr[e] * w2) * ivp[h], xc[e] * w2, part);
        }
        #pragma unroll
        for (int o = 16; o; o >>= 1)
            part += __shfl_xor_sync(0xffffffffu, part, o);
        if ((tid & 31) == 0) red[tid >> 5] = part;
        __syncthreads();
        if (tid == 0)
            exact_val = red[0] + red[1] + red[2] + red[3] +
                        red[4] + red[5] + red[6] + red[7];
        __syncthreads();
        if (tid == (c & 255)) v[c >> 8] = exact_val;
        __syncthreads();
    }

    // ---- standard masked softmax on (possibly corrected) v ----
    float m = -1e30f;
    #pragma unroll
    for (int i = 0; i < 8; i++)
        if (v[i] >= 0.1f) m = fmaxf(m, v[i]);
    #pragma unroll
    for (int o = 16; o; o >>= 1) m = fmaxf(m, __shfl_xor_sync(0xffffffffu, m, o));
    if ((tid & 31) == 0) red[tid >> 5] = m;
    __syncthreads();
    float M = fmaxf(fmaxf(fmaxf(red[0], red[1]), fmaxf(red[2], red[3])),
                    fmaxf(fmaxf(red[4], red[5]), fmaxf(red[6], red[7])));
    __syncthreads();

    float sum = 0.f;
    #pragma unroll
    for (int i = 0; i < 8; i++) {
        v[i] = (v[i] >= 0.1f) ? expf(v[i] - M) : 0.f;
        sum += v[i];
    }
    #pragma unroll
    for (int o = 16; o; o >>= 1) sum += __shfl_xor_sync(0xffffffffu, sum, o);
    if ((tid & 31) == 0) red[tid >> 5] = sum;
    __syncthreads();
    float T = red[0] + red[1] + red[2] + red[3] +
              red[4] + red[5] + red[6] + red[7];
    float inv = 1.f / T;

    #pragma unroll
    for (int i = 0; i < 8; i++)
        Phi[(size_t)r * L_DIM + tid + i * 256] = __float2half_rn(v[i] * inv);
}

// ===========================================================================
// mma1p: 1-pass fp16 GEMM, C = op(A[M,K] @ B[N,K]^T). 128x64 tile, 8 warps.
// EPI 0: fp32 row-major + relu (final out)
// EPI 1: fp16 row-major + relu (X1)
// EPI 2: fp16 TRANSPOSED [n][m], no relu (T^T)
// ===========================================================================
#define QA_B 16384
#define QB_B 8192
#define QSTAGE_B (QA_B + QB_B)
#define MMA_SMEM (3 * QSTAGE_B + 128)

template <int KDIM, int EPI>
__global__ void __launch_bounds__(256, 1) mma1p(
    const __half* __restrict__ A, const __half* __restrict__ B,
    float* __restrict__ Cf, __half* __restrict__ Ch)
{
    extern __shared__ char smem_raw[];
    const uint32_t sb = (smem_u32(smem_raw) + 127u) & ~127u;

    const int tid  = threadIdx.x;
    const int wid  = tid >> 5, lane = tid & 31;
    const int bm = blockIdx.y << 7;
    const int bn = blockIdx.x << 6;
    const int wm = wid >> 2, wn = wid & 3;

    float acc[4][2][4];
    #pragma unroll
    for (int mt = 0; mt < 4; mt++)
        #pragma unroll
        for (int nt = 0; nt < 2; nt++)
            #pragma unroll
            for (int f = 0; f < 4; f++) acc[mt][nt][f] = 0.f;

    uint32_t offA[4][4], offB[4];
    #pragma unroll
    for (int mt = 0; mt < 4; mt++) {
        int r  = wm * 64 + mt * 16 + (lane & 15);
        int r7 = r & 7;
        #pragma unroll
        for (int ks = 0; ks < 4; ks++) {
            int ch = ks * 2 + (lane >> 4);
            offA[mt][ks] = r * 128 + ((ch ^ r7) << 4);
        }
    }
    {
        int ntl = (lane >> 4) & 1;
        int r   = wn * 16 + ntl * 8 + (lane & 7);
        int r7  = r & 7;
        #pragma unroll
        for (int ks = 0; ks < 4; ks++) {
            int ch = ks * 2 + ((lane >> 3) & 1);
            offB[ks] = r * 128 + ((ch ^ r7) << 4);
        }
    }

    uint32_t dstA[4]; int srcA[4];
    #pragma unroll
    for (int t = 0; t < 4; t++) {
        int idx = tid + t * 256;
        int r = idx >> 3, ch = idx & 7;
        dstA[t] = (uint32_t)(r * 128 + ((ch ^ (r & 7)) << 4));
        srcA[t] = (bm + r) * KDIM + ch * 8;
    }
    uint32_t dstB[2]; int srcB[2];
    #pragma unroll
    for (int t = 0; t < 2; t++) {
        int idx = tid + t * 256;
        int r = idx >> 3, ch = idx & 7;
        dstB[t] = (uint32_t)(r * 128 + ((ch ^ (r & 7)) << 4));
        srcB[t] = (bn + r) * KDIM + ch * 8;
    }

    auto cp_stage = [&](int s, int kt) {
        const int k0 = kt << 6;
        const uint32_t base = sb + (uint32_t)s * QSTAGE_B;
        #pragma unroll
        for (int t = 0; t < 4; t++)
            CP_ASYNC16(base + dstA[t], A + srcA[t] + k0);
        #pragma unroll
        for (int t = 0; t < 2; t++)
            CP_ASYNC16(base + QA_B + dstB[t], B + srcB[t] + k0);
        CP_COMMIT();
    };

    auto compute = [&](int s) {
        const uint32_t pa = sb + (uint32_t)s * QSTAGE_B;
        #pragma unroll
        for (int ks = 0; ks < 4; ks++) {
            uint32_t ah[4][4], bh[4];
            #pragma unroll
            for (int mt = 0; mt < 4; mt++)
                ldsm_x4(ah[mt], pa + offA[mt][ks]);
            ldsm_x4(bh, pa + QA_B + offB[ks]);
            #pragma unroll
            for (int nt = 0; nt < 2; nt++)
                #pragma unroll
                for (int mt = 0; mt < 4; mt++)
                    mma_f16(acc[mt][nt], ah[mt], bh + 2 * nt);
        }
    };

    const int NKT = KDIM / 64;
    cp_stage(0, 0);
    cp_stage(1, 1);
    int sc = 0, s2 = 2;
    for (int kt = 0; kt < NKT; kt++) {
        if (kt + 1 < NKT) { CP_WAIT(1); } else { CP_WAIT(0); }
        __syncthreads();
        if (kt + 2 < NKT) cp_stage(s2, kt + 2);
        compute(sc);
        if (++sc == 3) sc = 0;
        if (++s2 == 3) s2 = 0;
    }

    #pragma unroll
    for (int mt = 0; mt < 4; mt++)
        #pragma unroll
        for (int nt = 0; nt < 2; nt++) {
            const int r0 = bm + wm * 64 + mt * 16 + (lane >> 2);
            const int c0 = bn + wn * 16 + nt * 8 + (lane & 3) * 2;
            const float* d = acc[mt][nt];
            if (EPI == 2) {
                #pragma unroll
                for (int f = 0; f < 4; f++) {
                    int rr = r0 + (f >> 1) * 8;
                    int cc = c0 + (f & 1);
                    Ch[(size_t)cc * L_DIM + rr] = __float2half_rn(d[f]);
                }
            } else {
                #pragma unroll
                for (int hrow = 0; hrow < 2; hrow++) {
                    float v0 = fmaxf(d[hrow * 2 + 0], 0.f);
                    float v1 = fmaxf(d[hrow * 2 + 1], 0.f);
                    int rr = r0 + hrow * 8;
                    if (EPI == 1) {
                        *(__half2*)(Ch + (size_t)rr * E_DIM + c0) =
                            __halves2half2(__float2half_rn(v0),
                                           __float2half_rn(v1));
                    } else {
                        *(float2*)(Cf + (size_t)rr * E_DIM + c0) =
                            make_float2(v0, v1);
                    }
                }
            }
        }
}

// ===========================================================================
// Launch
// ===========================================================================
extern "C" void kernel_launch(void* const* d_in, const int* in_sizes, int n_in,
                              void* d_out, int out_size)
{
    const float* Lemb = (const float*)d_in[0];
    const float* Xpt  = (const float*)d_in[1];
    const float* Wpt  = (const float*)d_in[2];
    const float* W0   = (const float*)d_in[3];
    const float* W1   = (const float*)d_in[4];
    float* out = (float*)d_out;

    float *S, *invs;
    __half *Zh, *Phi, *Ah, *Wt, *Th;
    cudaGetSymbolAddress((void**)&Zh,   g_Zh);
    cudaGetSymbolAddress((void**)&invs, g_inv);
    cudaGetSymbolAddress((void**)&S,    g_S);
    cudaGetSymbolAddress((void**)&Phi,  g_Phi);
    cudaGetSymbolAddress((void**)&Ah,   g_Ah);
    cudaGetSymbolAddress((void**)&Wt,   g_Wt);
    cudaGetSymbolAddress((void**)&Th,   g_Th);

    cudaFuncSetAttribute(zzt_mma, cudaFuncAttributeMaxDynamicSharedMemorySize,
                         ZZT_SMEM);
    cudaFuncSetAttribute(mma1p<E_DIM, 2>,
                         cudaFuncAttributeMaxDynamicSharedMemorySize, MMA_SMEM);
    cudaFuncSetAttribute(mma1p<L_DIM, 0>,
                         cudaFuncAttributeMaxDynamicSharedMemorySize, MMA_SMEM);
    cudaFuncSetAttribute(mma1p<L_DIM, 1>,
                         cudaFuncAttributeMaxDynamicSharedMemorySize, MMA_SMEM);

    const dim3 gcn_grid(E_DIM / 64, L_DIM / 128);

    // 1) prep: Zh + invs + Lemb fp16 + W^T fp16 (one launch)
    prep_all<<<PREP_GRID, 512>>>(Xpt, Wpt, Lemb, W0, W1, Zh, invs, Ah, Wt);

    // 2) scores = Z Z^T (single-pass fp16 mma), symmetric
    zzt_mma<<<dim3(16, 16), 256, ZZT_SMEM>>>(Zh, S);

    // 3) adj = softmax(threshold(scores)) with inline exact band fixup
    masked_softmax_fix<<<L_DIM, 256>>>(S, Xpt, Wpt, invs, Phi);

    // 4) T0t = (Lemb @ W0)^T fp16
    mma1p<E_DIM, 2><<<gcn_grid, 256, MMA_SMEM>>>(Ah, Wt, nullptr, Th);

    // 5) X1 = relu(adj @ T0) -> fp16 (overwrites Ah)
    mma1p<L_DIM, 1><<<gcn_grid, 256, MMA_SMEM>>>(Phi, Th, nullptr, Ah);

    // 6) T1t = (X1 @ W1)^T fp16
    mma1p<E_DIM, 2><<<gcn_grid, 256, MMA_SMEM>>>(
        Ah, Wt + (size_t)E_DIM * E_DIM, nullptr, Th);

    // 7) out = relu(adj @ T1) fp32
    mma1p<L_DIM, 0><<<gcn_grid, 256, MMA_SMEM>>>(Phi, Th, out, nullptr);
}

// round 14
// speedup vs baseline: 1.5354x; 1.0161x over previous
#include <cuda_runtime.h>
#include <cuda_fp16.h>
#include <math.h>
#include <stdint.h>

// Problem constants
#define L_DIM   2048
#define E_DIM   512
#define EPT_DIM 300
#define H_DIM   16
#define KBIG    (H_DIM * EPT_DIM)   // 4800

#define BANDW 1e-4f

// Scratch (allocation-free rule: __device__ globals)
__device__ __half g_Zh [L_DIM * KBIG];   // fp16 Z (zzt input)
__device__ float  g_inv[L_DIM * H_DIM];  // per-(l,h) 0.25/norm
__device__ float  g_S  [L_DIM * L_DIM];  // scores
__device__ __half g_Phi[L_DIM * L_DIM];  // adj fp16
__device__ __half g_Ah [L_DIM * E_DIM];  // Lemb / X1 fp16
__device__ __half g_Wt [2 * E_DIM * E_DIM]; // W0^T, W1^T fp16
__device__ __half g_Th [E_DIM * L_DIM];  // T^T fp16 (B operand of gcn)

// ===========================================================================
// Helpers
// ===========================================================================
__device__ __forceinline__ uint32_t smem_u32(const void* p) {
    uint32_t a;
    asm("{ .reg .u64 t; cvta.to.shared.u64 t, %1; cvt.u32.u64 %0, t; }"
        : "=r"(a) : "l"(p));
    return a;
}
__device__ __forceinline__ void ldsm_x4(uint32_t* r, uint32_t addr) {
    asm volatile("ldmatrix.sync.aligned.m8n8.x4.shared.b16 {%0,%1,%2,%3}, [%4];"
                 : "=r"(r[0]), "=r"(r[1]), "=r"(r[2]), "=r"(r[3]) : "r"(addr));
}
__device__ __forceinline__ void mma_f16(float* d, const uint32_t* a,
                                        const uint32_t* b) {
    asm volatile("mma.sync.aligned.m16n8k16.row.col.f32.f16.f16.f32 "
                 "{%0,%1,%2,%3}, {%4,%5,%6,%7}, {%8,%9}, {%0,%1,%2,%3};"
                 : "+f"(d[0]), "+f"(d[1]), "+f"(d[2]), "+f"(d[3])
                 : "r"(a[0]), "r"(a[1]), "r"(a[2]), "r"(a[3]),
                   "r"(b[0]), "r"(b[1]));
}
#define CP_ASYNC16(dst, src) \
    asm volatile("cp.async.cg.shared.global [%0], [%1], 16;" \
                 :: "r"(dst), "l"(src))
#define CP_COMMIT()  asm volatile("cp.async.commit_group;" ::: "memory")
#define CP_WAIT(N)   asm volatile("cp.async.wait_group " #N ";" ::: "memory")

// ===========================================================================
// Kernel 1: prep_all — compute_z + Lemb->fp16 + W0^T/W1^T->fp16, one launch.
// ===========================================================================
#define PREP_ZB   L_DIM              // 2048
#define PREP_LB   512
#define PREP_WB   256
#define PREP_GRID (PREP_ZB + PREP_LB + PREP_WB)

__global__ __launch_bounds__(512) void prep_all(
    const float* __restrict__ xpt, const float* __restrict__ Wpt,
    const float* __restrict__ Lemb,
    const float* __restrict__ W0, const float* __restrict__ W1,
    __half* __restrict__ Zh, float* __restrict__ invs,
    __half* __restrict__ Ah, __half* __restrict__ Wt)
{
    __shared__ float tbuf[2][32][33];
    const int blk = blockIdx.x;

    if (blk < PREP_ZB) {
        const int l    = blk;
        const int h    = threadIdx.x >> 5;
        const int lane = threadIdx.x & 31;
        const float* xrow = xpt + (size_t)l * EPT_DIM;
        const float* wrow = Wpt + h * EPT_DIM;

        float v0[5], v1[5];
        float ss = 0.f;
        #pragma unroll
        for (int i = 0; i < 5; i++) {
            int p = lane + i * 32;
            float a = 0.f, b = 0.f;
            if (p < EPT_DIM / 2) {
                int e = 2 * p;
                float w0 = wrow[e], w1 = wrow[e + 1];
                a = xrow[e] * w0 * w0;
                b = xrow[e + 1] * w1 * w1;
            }
            v0[i] = a; v1[i] = b;
            ss += a * a + b * b;
        }
        #pragma unroll
        for (int o = 16; o; o >>= 1) ss += __shfl_xor_sync(0xffffffffu, ss, o);
        float inv = 0.25f / fmaxf(sqrtf(ss), 1e-12f);
        if (lane == 0) invs[l * H_DIM + h] = inv;

        size_t base = (size_t)l * KBIG + h * EPT_DIM;
        #pragma unroll
        for (int i = 0; i < 5; i++) {
            int p = lane + i * 32;
            if (p < EPT_DIM / 2) {
                __half2 hv = __halves2half2(__float2half_rn(v0[i] * inv),
                                            __float2half_rn(v1[i] * inv));
                *(__half2*)(Zh + base + 2 * p) = hv;
            }
        }
    } else if (blk < PREP_ZB + PREP_LB) {
        int i4 = ((blk - PREP_ZB) * 512 + threadIdx.x) * 4;
        float4 v = *(const float4*)(Lemb + i4);
        __half2 h0 = __halves2half2(__float2half_rn(v.x), __float2half_rn(v.y));
        __half2 h1 = __halves2half2(__float2half_rn(v.z), __float2half_rn(v.w));
        *(__half2*)(Ah + i4)     = h0;
        *(__half2*)(Ah + i4 + 2) = h1;
    } else {
        int b    = blk - PREP_ZB - PREP_LB;
        int hf   = threadIdx.x >> 8;
        int t256 = threadIdx.x & 255;
        int tile = b * 2 + hf;
        int z    = tile >> 8;
        int rem  = tile & 255;
        int by   = (rem >> 4) * 32, bx = (rem & 15) * 32;
        const float* W = z ? W1 : W0;
        __half* wt = Wt + (size_t)z * E_DIM * E_DIM;
        const int x = t256 & 31, y4 = (t256 >> 5) * 4;
        #pragma unroll
        for (int i = 0; i < 4; i++)
            tbuf[hf][y4 + i][x] = W[(size_t)(by + y4 + i) * E_DIM + bx + x];
        __syncthreads();
        #pragma unroll
        for (int i = 0; i < 4; i++) {
            float v = tbuf[hf][x][y4 + i];
            wt[(size_t)(bx + y4 + i) * E_DIM + by + x] = __float2half_rn(v);
        }
    }
}

// ===========================================================================
// Kernel 2: ZZ^T single-pass fp16 mma.sync; pair-wise k-tiles (2 per barrier),
// 3 pair-slots (6 tile-stages) of cp.async; symmetric.
// ===========================================================================
#define TILE_B   16384
#define STAGE_B  (2 * TILE_B)              // one tile-stage (A+B): 32 KB
#define PAIR_B   (2 * STAGE_B)             // one pair-slot: 64 KB
#define ZZT_SMEM (3 * PAIR_B + 128)        // 196736 B

__global__ void __launch_bounds__(256, 1) zzt_mma(
    const __half* __restrict__ Zh, float* __restrict__ S)
{
    const int bx = blockIdx.x, by = blockIdx.y;
    if (bx < by) return;
    extern __shared__ char smem_raw[];
    const uint32_t sb = (smem_u32(smem_raw) + 127u) & ~127u;

    const int tid  = threadIdx.x;
    const int wid  = tid >> 5, lane = tid & 31;
    const int bm = by << 7, bn = bx << 7;
    const int wm = wid >> 2, wn = wid & 3;

    float acc[4][4][4];
    #pragma unroll
    for (int mt = 0; mt < 4; mt++)
        #pragma unroll
        for (int nt = 0; nt < 4; nt++)
            #pragma unroll
            for (int f = 0; f < 4; f++) acc[mt][nt][f] = 0.f;

    uint32_t offA[4][4], offBp[2][4];
    #pragma unroll
    for (int mt = 0; mt < 4; mt++) {
        int r  = wm * 64 + mt * 16 + (lane & 15);
        int r7 = r & 7;
        #pragma unroll
        for (int ks = 0; ks < 4; ks++) {
            int ch = ks * 2 + (lane >> 4);
            offA[mt][ks] = r * 128 + ((ch ^ r7) << 4);
        }
    }
    #pragma unroll
    for (int p = 0; p < 2; p++) {
        int ntl = p * 2 + ((lane >> 4) & 1);
        int r   = wn * 32 + ntl * 8 + (lane & 7);
        int r7  = r & 7;
        #pragma unroll
        for (int ks = 0; ks < 4; ks++) {
            int ch = ks * 2 + ((lane >> 3) & 1);
            offBp[p][ks] = r * 128 + ((ch ^ r7) << 4);
        }
    }

    uint32_t dstoff[4];
    int      srcA[4], srcB[4];
    #pragma unroll
    for (int t = 0; t < 4; t++) {
        int idx = tid + t * 256;
        int r = idx >> 3, ch = idx & 7;
        dstoff[t] = (uint32_t)(r * 128 + ((ch ^ (r & 7)) << 4));
        srcA[t] = (bm + r) * KBIG + ch * 8;
        srcB[t] = (bn + r) * KBIG + ch * 8;
    }

    const int NKT   = KBIG / 64;     // 75
    const int NPAIR = (NKT + 1) / 2; // 38

    auto cp_tile = [&](uint32_t base, int kt) {
        const int k0 = kt << 6;
        #pragma unroll
        for (int t = 0; t < 4; t++) {
            CP_ASYNC16(base + dstoff[t],          Zh + srcA[t] + k0);
            CP_ASYNC16(base + TILE_B + dstoff[t], Zh + srcB[t] + k0);
        }
    };
    auto cp_pair = [&](int p) {
        uint32_t base = sb + (uint32_t)(p % 3) * PAIR_B;
        cp_tile(base, 2 * p);
        if (2 * p + 1 < NKT) cp_tile(base + STAGE_B, 2 * p + 1);
        CP_COMMIT();
    };

    auto compute = [&](uint32_t pa) {
        #pragma unroll
        for (int ks = 0; ks < 4; ks++) {
            uint32_t ah[4][4];
            #pragma unroll
            for (int mt = 0; mt < 4; mt++)
                ldsm_x4(ah[mt], pa + offA[mt][ks]);
            #pragma unroll
            for (int p = 0; p < 2; p++) {
                uint32_t bh[4];
                ldsm_x4(bh, pa + TILE_B + offBp[p][ks]);
                #pragma unroll
                for (int half = 0; half < 2; half++) {
                    int nt = p * 2 + half;
                    #pragma unroll
                    for (int mt = 0; mt < 4; mt++)
                        mma_f16(acc[mt][nt], ah[mt], bh + 2 * half);
                }
            }
        }
    };

    cp_pair(0);
    cp_pair(1);
    for (int p = 0; p < NPAIR; p++) {
        if (p + 1 < NPAIR) { CP_WAIT(1); } else { CP_WAIT(0); }
        __syncthreads();
        if (p + 2 < NPAIR) cp_pair(p + 2);
        uint32_t base = sb + (uint32_t)(p % 3) * PAIR_B;
        compute(base);
        if (2 * p + 1 < NKT) compute(base + STAGE_B);
    }

    #pragma unroll
    for (int mt = 0; mt < 4; mt++)
        #pragma unroll
        for (int nt = 0; nt < 4; nt++) {
            const int r0 = bm + wm * 64 + mt * 16 + (lane >> 2);
            const int c0 = bn + wn * 32 + nt * 8 + (lane & 3) * 2;
            const float* d = acc[mt][nt];
            *(float2*)(S + (size_t)r0 * L_DIM + c0)       = make_float2(d[0], d[1]);
            *(float2*)(S + (size_t)(r0 + 8) * L_DIM + c0) = make_float2(d[2], d[3]);
            if (bx != by) {
                S[(size_t)c0 * L_DIM + r0]           = d[0];
                S[(size_t)(c0 + 1) * L_DIM + r0]     = d[1];
                S[(size_t)c0 * L_DIM + r0 + 8]       = d[2];
                S[(size_t)(c0 + 1) * L_DIM + r0 + 8] = d[3];
            }
        }
}

// ===========================================================================
// Kernel 3: masked softmax with inline exact fixup of near-threshold entries.
// ===========================================================================
#define MAXROWBAND 32

__global__ __launch_bounds__(256) void masked_softmax_fix(
    const float* __restrict__ S,
    const float* __restrict__ xpt, const float* __restrict__ Wpt,
    const float* __restrict__ invs, __half* __restrict__ Phi)
{
    __shared__ float red[8];
    __shared__ int   bcols[MAXROWBAND];
    __shared__ int   bcnt;
    __shared__ float ivp[H_DIM];
    __shared__ float exact_val;

    const int r   = blockIdx.x;
    const int tid = threadIdx.x;
    const float* row = S + (size_t)r * L_DIM;

    float v[8];
    #pragma unroll
    for (int i = 0; i < 8; i++) v[i] = row[tid + i * 256];

    if (tid == 0) bcnt = 0;
    __syncthreads();
    #pragma unroll
    for (int i = 0; i < 8; i++) {
        if (fabsf(v[i] - 0.1f) < BANDW) {
            int p = atomicAdd(&bcnt, 1);
            if (p < MAXROWBAND) bcols[p] = tid + i * 256;
        }
    }
    __syncthreads();

    int nb = bcnt; if (nb > MAXROWBAND) nb = MAXROWBAND;
    for (int b = 0; b < nb; b++) {
        int c = bcols[b];
        if (tid < H_DIM)
            ivp[tid] = invs[r * H_DIM + tid] * invs[c * H_DIM + tid];
        __syncthreads();
        const float* xr = xpt + (size_t)r * EPT_DIM;
        const float* xc = xpt + (size_t)c * EPT_DIM;
        float part = 0.f;
        for (int g = tid; g < KBIG; g += 256) {
            int h = g / EPT_DIM;
            int e = g - h * EPT_DIM;
            float w = Wpt[g];
            float w2 = w * w;
            part = fmaf((xr[e] * w2) * ivp[h], xc[e] * w2, part);
        }
        #pragma unroll
        for (int o = 16; o; o >>= 1)
            part += __shfl_xor_sync(0xffffffffu, part, o);
        if ((tid & 31) == 0) red[tid >> 5] = part;
        __syncthreads();
        if (tid == 0)
            exact_val = red[0] + red[1] + red[2] + red[3] +
                        red[4] + red[5] + red[6] + red[7];
        __syncthreads();
        if (tid == (c & 255)) v[c >> 8] = exact_val;
        __syncthreads();
    }

    float m = -1e30f;
    #pragma unroll
    for (int i = 0; i < 8; i++)
        if (v[i] >= 0.1f) m = fmaxf(m, v[i]);
    #pragma unroll
    for (int o = 16; o; o >>= 1) m = fmaxf(m, __shfl_xor_sync(0xffffffffu, m, o));
    if ((tid & 31) == 0) red[tid >> 5] = m;
    __syncthreads();
    float M = fmaxf(fmaxf(fmaxf(red[0], red[1]), fmaxf(red[2], red[3])),
                    fmaxf(fmaxf(red[4], red[5]), fmaxf(red[6], red[7])));
    __syncthreads();

    float sum = 0.f;
    #pragma unroll
    for (int i = 0; i < 8; i++) {
        v[i] = (v[i] >= 0.1f) ? expf(v[i] - M) : 0.f;
        sum += v[i];
    }
    #pragma unroll
    for (int o = 16; o; o >>= 1) sum += __shfl_xor_sync(0xffffffffu, sum, o);
    if ((tid & 31) == 0) red[tid >> 5] = sum;
    __syncthreads();
    float T = red[0] + red[1] + red[2] + red[3] +
              red[4] + red[5] + red[6] + red[7];
    float inv = 1.f / T;

    #pragma unroll
    for (int i = 0; i < 8; i++)
        Phi[(size_t)r * L_DIM + tid + i * 256] = __float2half_rn(v[i] * inv);
}

// ===========================================================================
// mma1p: 1-pass fp16 GEMM, pair-wise k-tiles, 3 pair-slots.
// EPI 0: fp32 row-major + relu; EPI 1: fp16 row-major + relu;
// EPI 2: fp16 transposed [n][m], no relu.
// ===========================================================================
#define QA_B 16384
#define QB_B 8192
#define QSTAGE_B (QA_B + QB_B)             // 24 KB
#define QPAIR_B  (2 * QSTAGE_B)            // 48 KB
#define MMA_SMEM (3 * QPAIR_B + 128)       // 147584 B

template <int KDIM, int EPI>
__global__ void __launch_bounds__(256, 1) mma1p(
    const __half* __restrict__ A, const __half* __restrict__ B,
    float* __restrict__ Cf, __half* __restrict__ Ch)
{
    extern __shared__ char smem_raw[];
    const uint32_t sb = (smem_u32(smem_raw) + 127u) & ~127u;

    const int tid  = threadIdx.x;
    const int wid  = tid >> 5, lane = tid & 31;
    const int bm = blockIdx.y << 7;
    const int bn = blockIdx.x << 6;
    const int wm = wid >> 2, wn = wid & 3;

    float acc[4][2][4];
    #pragma unroll
    for (int mt = 0; mt < 4; mt++)
        #pragma unroll
        for (int nt = 0; nt < 2; nt++)
            #pragma unroll
            for (int f = 0; f < 4; f++) acc[mt][nt][f] = 0.f;

    uint32_t offA[4][4], offB[4];
    #pragma unroll
    for (int mt = 0; mt < 4; mt++) {
        int r  = wm * 64 + mt * 16 + (lane & 15);
        int r7 = r & 7;
        #pragma unroll
        for (int ks = 0; ks < 4; ks++) {
            int ch = ks * 2 + (lane >> 4);
            offA[mt][ks] = r * 128 + ((ch ^ r7) << 4);
        }
    }
    {
        int ntl = (lane >> 4) & 1;
        int r   = wn * 16 + ntl * 8 + (lane & 7);
        int r7  = r & 7;
        #pragma unroll
        for (int ks = 0; ks < 4; ks++) {
            int ch = ks * 2 + ((lane >> 3) & 1);
            offB[ks] = r * 128 + ((ch ^ r7) << 4);
        }
    }

    uint32_t dstA[4]; int srcA[4];
    #pragma unroll
    for (int t = 0; t < 4; t++) {
        int idx = tid + t * 256;
        int r = idx >> 3, ch = idx & 7;
        dstA[t] = (uint32_t)(r * 128 + ((ch ^ (r & 7)) << 4));
        srcA[t] = (bm + r) * KDIM + ch * 8;
    }
    uint32_t dstB[2]; int srcB[2];
    #pragma unroll
    for (int t = 0; t < 2; t++) {
        int idx = tid + t * 256;
        int r = idx >> 3, ch = idx & 7;
        dstB[t] = (uint32_t)(r * 128 + ((ch ^ (r & 7)) << 4));
        srcB[t] = (bn + r) * KDIM + ch * 8;
    }

    const int NKT   = KDIM / 64;
    const int NPAIR = NKT / 2;       // KDIM multiple of 128 everywhere

    auto cp_tile = [&](uint32_t base, int kt) {
        const int k0 = kt << 6;
        #pragma unroll
        for (int t = 0; t < 4; t++)
            CP_ASYNC16(base + dstA[t], A + srcA[t] + k0);
        #pragma unroll
        for (int t = 0; t < 2; t++)
            CP_ASYNC16(base + QA_B + dstB[t], B + srcB[t] + k0);
    };
    auto cp_pair = [&](int p) {
        uint32_t base = sb + (uint32_t)(p % 3) * QPAIR_B;
        cp_tile(base, 2 * p);
        cp_tile(base + QSTAGE_B, 2 * p + 1);
        CP_COMMIT();
    };

    auto compute = [&](uint32_t pa) {
        #pragma unroll
        for (int ks = 0; ks < 4; ks++) {
            uint32_t ah[4][4], bh[4];
            #pragma unroll
            for (int mt = 0; mt < 4; mt++)
                ldsm_x4(ah[mt], pa + offA[mt][ks]);
            ldsm_x4(bh, pa + QA_B + offB[ks]);
            #pragma unroll
            for (int nt = 0; nt < 2; nt++)
                #pragma unroll
                for (int mt = 0; mt < 4; mt++)
                    mma_f16(acc[mt][nt], ah[mt], bh + 2 * nt);
        }
    };

    cp_pair(0);
    if (NPAIR > 1) cp_pair(1);
    for (int p = 0; p < NPAIR; p++) {
        if (p + 1 < NPAIR) { CP_WAIT(1); } else { CP_WAIT(0); }
        __syncthreads();
        if (p + 2 < NPAIR) cp_pair(p + 2);
        uint32_t base = sb + (uint32_t)(p % 3) * QPAIR_B;
        compute(base);
        compute(base + QSTAGE_B);
    }

    #pragma unroll
    for (int mt = 0; mt < 4; mt++)
        #pragma unroll
        for (int nt = 0; nt < 2; nt++) {
            const int r0 = bm + wm * 64 + mt * 16 + (lane >> 2);
            const int c0 = bn + wn * 16 + nt * 8 + (lane & 3) * 2;
            const float* d = acc[mt][nt];
            if (EPI == 2) {
                #pragma unroll
                for (int f = 0; f < 4; f++) {
                    int rr = r0 + (f >> 1) * 8;
                    int cc = c0 + (f & 1);
                    Ch[(size_t)cc * L_DIM + rr] = __float2half_rn(d[f]);
                }
            } else {
                #pragma unroll
                for (int hrow = 0; hrow < 2; hrow++) {
                    float v0 = fmaxf(d[hrow * 2 + 0], 0.f);
                    float v1 = fmaxf(d[hrow * 2 + 1], 0.f);
                    int rr = r0 + hrow * 8;
                    if (EPI == 1) {
                        *(__half2*)(Ch + (size_t)rr * E_DIM + c0) =
                            __halves2half2(__float2half_rn(v0),
                                           __float2half_rn(v1));
                    } else {
                        *(float2*)(Cf + (size_t)rr * E_DIM + c0) =
                            make_float2(v0, v1);
                    }
                }
            }
        }
}

// ===========================================================================
// Launch
// ===========================================================================
extern "C" void kernel_launch(void* const* d_in, const int* in_sizes, int n_in,
                              void* d_out, int out_size)
{
    const float* Lemb = (const float*)d_in[0];
    const float* Xpt  = (const float*)d_in[1];
    const float* Wpt  = (const float*)d_in[2];
    const float* W0   = (const float*)d_in[3];
    const float* W1   = (const float*)d_in[4];
    float* out = (float*)d_out;

    float *S, *invs;
    __half *Zh, *Phi, *Ah, *Wt, *Th;
    cudaGetSymbolAddress((void**)&Zh,   g_Zh);
    cudaGetSymbolAddress((void**)&invs, g_inv);
    cudaGetSymbolAddress((void**)&S,    g_S);
    cudaGetSymbolAddress((void**)&Phi,  g_Phi);
    cudaGetSymbolAddress((void**)&Ah,   g_Ah);
    cudaGetSymbolAddress((void**)&Wt,   g_Wt);
    cudaGetSymbolAddress((void**)&Th,   g_Th);

    cudaFuncSetAttribute(zzt_mma, cudaFuncAttributeMaxDynamicSharedMemorySize,
                         ZZT_SMEM);
    cudaFuncSetAttribute(mma1p<E_DIM, 2>,
                         cudaFuncAttributeMaxDynamicSharedMemorySize, MMA_SMEM);
    cudaFuncSetAttribute(mma1p<L_DIM, 0>,
                         cudaFuncAttributeMaxDynamicSharedMemorySize, MMA_SMEM);
    cudaFuncSetAttribute(mma1p<L_DIM, 1>,
                         cudaFuncAttributeMaxDynamicSharedMemorySize, MMA_SMEM);

    const dim3 gcn_grid(E_DIM / 64, L_DIM / 128);

    // 1) prep: Zh + invs + Lemb fp16 + W^T fp16 (one launch)
    prep_all<<<PREP_GRID, 512>>>(Xpt, Wpt, Lemb, W0, W1, Zh, invs, Ah, Wt);

    // 2) scores = Z Z^T (single-pass fp16 mma), symmetric, pair-pipelined
    zzt_mma<<<dim3(16, 16), 256, ZZT_SMEM>>>(Zh, S);

    // 3) adj = softmax(threshold(scores)) with inline exact band fixup
    masked_softmax_fix<<<L_DIM, 256>>>(S, Xpt, Wpt, invs, Phi);

    // 4) T0t = (Lemb @ W0)^T fp16
    mma1p<E_DIM, 2><<<gcn_grid, 256, MMA_SMEM>>>(Ah, Wt, nullptr, Th);

    // 5) X1 = relu(adj @ T0) -> fp16 (overwrites Ah)
    mma1p<L_DIM, 1><<<gcn_grid, 256, MMA_SMEM>>>(Phi, Th, nullptr, Ah);

    // 6) T1t = (X1 @ W1)^T fp16
    mma1p<E_DIM, 2><<<gcn_grid, 256, MMA_SMEM>>>(
        Ah, Wt + (size_t)E_DIM * E_DIM, nullptr, Th);

    // 7) out = relu(adj @ T1) fp32
    mma1p<L_DIM, 0><<<gcn_grid, 256, MMA_SMEM>>>(Phi, Th, out, nullptr);
}